// round 6
// baseline (speedup 1.0000x reference)
#include <cuda_runtime.h>
#include <math.h>
#include <stdint.h>

#define S_SEQ 256
#define R_RES 256
#define CM 256
#define CZ 128
#define NH 8
#define CH 32
#define HC 256
#define LNEPS 1e-5f

// ---------------- scratch (device globals; no allocation allowed) ----------------
// fragment layout for a 32-row x 8-col chunk (rb = row/32, kc = col/8):
//   offset = (rb*32 + kc)*256 + mt*128 + lane*4 + f
//   where row = rb*32 + mt*16 + sub*8 + (lane>>2), col = kc*8 + half*4 + (lane&3),
//         f = sub + 2*half   (matches mma.m16n8k8 A-fragment regs a[0..3])
__device__ float g_mnf[(size_t)S_SEQ * R_RES * CM];      // 64 MB  LN(m), tf32, frag layout
__device__ float g_q[(size_t)S_SEQ * NH * R_RES * CH];   // 64 MB  (s,h,r,c)
__device__ float g_k[(size_t)S_SEQ * NH * R_RES * CH];   // 64 MB
__device__ float g_v[(size_t)S_SEQ * NH * R_RES * CH];   // 64 MB
__device__ float g_gate[(size_t)S_SEQ * R_RES * HC];     // 64 MB  sigmoid(mn@Wg+bg), normal layout
__device__ float g_of[(size_t)S_SEQ * R_RES * HC];       // 64 MB  gate .* attn_out, tf32, frag layout
__device__ float g_bias[(size_t)NH * R_RES * R_RES];     //  2 MB  [h][q][k]
__device__ float2 g_wf[5 * 32768];                       //  2.5 MB B frags [z][kt][nb][ks][nt][lane]

__device__ __forceinline__ float ftf32(float x) {
    uint32_t u;
    asm("cvt.rna.tf32.f32 %0, %1;" : "=r"(u) : "f"(x));
    return __uint_as_float(u);
}
__device__ __forceinline__ uint32_t ftf32u(float x) {
    uint32_t u;
    asm("cvt.rna.tf32.f32 %0, %1;" : "=r"(u) : "f"(x));
    return u;
}
__device__ __forceinline__ uint32_t smem_u32(const void* p) {
    uint32_t a;
    asm("{ .reg .u64 t; cvta.to.shared.u64 t, %1; cvt.u32.u64 %0, t; }" : "=r"(a) : "l"(p));
    return a;
}
__device__ __forceinline__ void cp16(uint32_t dst, const void* src) {
    asm volatile("cp.async.cg.shared.global [%0], [%1], 16;" :: "r"(dst), "l"(src));
}

#define MMA4(d, a, b)                                                              \
    asm volatile("mma.sync.aligned.m16n8k8.row.col.f32.tf32.tf32.f32 "             \
                 "{%0,%1,%2,%3},{%4,%5,%6,%7},{%8,%9},{%0,%1,%2,%3};"              \
                 : "+f"(d[0]), "+f"(d[1]), "+f"(d[2]), "+f"(d[3])                  \
                 : "r"(a[0]), "r"(a[1]), "r"(a[2]), "r"(a[3]), "r"(b[0]), "r"(b[1]))

// ---------------- LayerNorm m -> fragment-ordered tf32 g_mnf ----------------
// one CTA = one 32-row fragment block; smem transpose for coalesced frag writes
__global__ void __launch_bounds__(256) ln_m_kernel(const float* __restrict__ x,
                                                   const float* __restrict__ w,
                                                   const float* __restrict__ b) {
    __shared__ float sln[32 * 260];
    const int tid = threadIdx.x;
    const int wid = tid >> 5, lane = tid & 31;

    const float4 w0 = *(const float4*)(w + lane * 8);
    const float4 w1 = *(const float4*)(w + lane * 8 + 4);
    const float4 b0 = *(const float4*)(b + lane * 8);
    const float4 b1 = *(const float4*)(b + lane * 8 + 4);

#pragma unroll 1
    for (int q = 0; q < 4; q++) {
        int lr = wid * 4 + q;
        size_t row = (size_t)blockIdx.x * 32 + lr;
        const float* xp = x + row * CM + lane * 8;
        float4 v0 = *(const float4*)xp;
        float4 v1 = *(const float4*)(xp + 4);
        float s  = v0.x + v0.y + v0.z + v0.w + v1.x + v1.y + v1.z + v1.w;
        float sq = v0.x * v0.x + v0.y * v0.y + v0.z * v0.z + v0.w * v0.w
                 + v1.x * v1.x + v1.y * v1.y + v1.z * v1.z + v1.w * v1.w;
#pragma unroll
        for (int st = 16; st > 0; st >>= 1) {
            s  += __shfl_xor_sync(0xffffffff, s, st);
            sq += __shfl_xor_sync(0xffffffff, sq, st);
        }
        float mean = s * (1.0f / CM);
        float inv  = rsqrtf(sq * (1.0f / CM) - mean * mean + LNEPS);
        float* sp = &sln[lr * 260 + lane * 8];
        sp[0] = ftf32((v0.x - mean) * inv * w0.x + b0.x);
        sp[1] = ftf32((v0.y - mean) * inv * w0.y + b0.y);
        sp[2] = ftf32((v0.z - mean) * inv * w0.z + b0.z);
        sp[3] = ftf32((v0.w - mean) * inv * w0.w + b0.w);
        sp[4] = ftf32((v1.x - mean) * inv * w1.x + b1.x);
        sp[5] = ftf32((v1.y - mean) * inv * w1.y + b1.y);
        sp[6] = ftf32((v1.z - mean) * inv * w1.z + b1.z);
        sp[7] = ftf32((v1.w - mean) * inv * w1.w + b1.w);
    }
    __syncthreads();

    float* dst = g_mnf + (size_t)blockIdx.x * 8192;
#pragma unroll
    for (int it = 0; it < 8; it++) {
        int i = tid + it * 256;
        int f = i * 4;
        int kc = f >> 8, rem = f & 255;
        int mt = rem >> 7, lp = (rem >> 2) & 31;
        int gid2 = lp >> 2, tg2 = lp & 3;
        int cb = kc * 8 + tg2;
        float4 v;
        v.x = sln[(mt * 16 + 0 + gid2) * 260 + cb];        // sub0 half0
        v.y = sln[(mt * 16 + 8 + gid2) * 260 + cb];        // sub1 half0
        v.z = sln[(mt * 16 + 0 + gid2) * 260 + cb + 4];    // sub0 half1
        v.w = sln[(mt * 16 + 8 + gid2) * 260 + cb + 4];    // sub1 half1
        *(float4*)(dst + f) = v;
    }
}

// ---------------- LN(z) + pair-bias: one warp per (q,k) ----------------
__global__ void __launch_bounds__(256) ln_z_bias_kernel(
    const float* __restrict__ z, const float* __restrict__ w,
    const float* __restrict__ b, const float* __restrict__ Wz) {
    __shared__ float sWzT[8 * 128];
    const int tid = threadIdx.x;
    for (int i = tid; i < 1024; i += 256) {
        int zz = i >> 3, h = i & 7;
        sWzT[h * 128 + zz] = Wz[i];
    }
    __syncthreads();

    const int wid = tid >> 5, lane = tid & 31;
    const int qk = blockIdx.x * 8 + wid;
    const int q = qk >> 8, k = qk & 255;
    float4 v = *(const float4*)(z + (size_t)qk * CZ + 4 * lane);
    float s  = v.x + v.y + v.z + v.w;
    float sq = v.x * v.x + v.y * v.y + v.z * v.z + v.w * v.w;
#pragma unroll
    for (int st = 16; st > 0; st >>= 1) {
        s  += __shfl_xor_sync(0xffffffff, s, st);
        sq += __shfl_xor_sync(0xffffffff, sq, st);
    }
    float mean = s * (1.0f / CZ);
    float inv  = rsqrtf(sq * (1.0f / CZ) - mean * mean + LNEPS);
    float4 w4 = *(const float4*)(w + 4 * lane);
    float4 b4 = *(const float4*)(b + 4 * lane);
    float4 zn;
    zn.x = (v.x - mean) * inv * w4.x + b4.x;
    zn.y = (v.y - mean) * inv * w4.y + b4.y;
    zn.z = (v.z - mean) * inv * w4.z + b4.z;
    zn.w = (v.w - mean) * inv * w4.w + b4.w;

    float p[8];
#pragma unroll
    for (int h = 0; h < 8; h++) {
        float4 wz = *(const float4*)&sWzT[h * 128 + 4 * lane];
        p[h] = zn.x * wz.x + zn.y * wz.y + zn.z * wz.z + zn.w * wz.w;
    }
#pragma unroll
    for (int st = 16; st > 0; st >>= 1) {
#pragma unroll
        for (int h = 0; h < 8; h++) p[h] += __shfl_xor_sync(0xffffffff, p[h], st);
    }
    float outv = p[0];
#pragma unroll
    for (int h = 1; h < 8; h++) if (lane == h) outv = p[h];
    if (lane < 8)
        g_bias[((size_t)lane * R_RES + q) * R_RES + k] = outv;
}

// ---------------- B-fragment repack: [zz][kt][nb][ks][nt][lane] float2 ----------------
__global__ void __launch_bounds__(256) repack_kernel(
    const float* __restrict__ w0, const float* __restrict__ w1,
    const float* __restrict__ w2, const float* __restrict__ w3,
    const float* __restrict__ w4) {
    int t = blockIdx.x * 256 + threadIdx.x;       // < 163840
    int lane = t & 31;
    int nt = (t >> 5) & 3;
    int ks = (t >> 7) & 3;
    int nb = (t >> 9) & 7;
    int kt = (t >> 12) & 7;
    int zz = t >> 15;
    const float* W = (zz == 0) ? w0 : (zz == 1) ? w1 : (zz == 2) ? w2 : (zz == 3) ? w3 : w4;
    int krow = kt * 32 + ks * 8 + (lane & 3);
    int ncol = nb * 32 + nt * 8 + (lane >> 2);
    float2 v;
    v.x = ftf32(W[krow * 256 + ncol]);
    v.y = ftf32(W[(krow + 4) * 256 + ncol]);
    g_wf[t] = v;
}

// ---------------- cp.async-pipelined tf32 GEMM: C(65536x256) = A @ W ----------------
// fused==1: blockIdx.x = nbp*4+z; z=0/1/2 -> q/k/v (permuted), z=3 -> gate (sigmoid+bg)
// fused==0: A = g_of (gate .* o, pre-multiplied by attn epilogue), out = d_out + bo
#define ASTAGE_F 4096
#define BSTAGE_F 2048
#define STAGE_F  6144
#define SM_BYTES (3 * STAGE_F * 4)   // 73728

__device__ __forceinline__ void stage_tile(uint32_t smb, int buf, int kt, int by, int nbp,
                                           int tid, const float* Af, const float2* Bw) {
    uint32_t db = smb + (uint32_t)buf * (STAGE_F * 4);
#pragma unroll
    for (int it = 0; it < 4; it++) {
        int ca = tid + it * 256;
        int rb = ca >> 8, kc = (ca >> 6) & 3, c = ca & 63;
        const float* s = Af + ((size_t)(by * 128 + rb * 32 + kt * 4 + kc)) * 256 + c * 4;
        cp16(db + (uint32_t)(((rb * 4 + kc) * 256 + c * 4) * 4), s);
    }
#pragma unroll
    for (int it = 0; it < 2; it++) {
        int cb = tid + it * 256;
        int nl = cb >> 8, inner = cb & 255;
        const float2* s = Bw + ((size_t)(kt * 8 + nbp * 2 + nl)) * 512 + inner * 2;
        cp16(db + (uint32_t)((ASTAGE_F + nl * 1024 + inner * 4) * 4), s);
    }
}

__global__ void __launch_bounds__(256, 2) tf32gemm_kernel(
    const float* __restrict__ bias_g, const float* __restrict__ bias_o,
    float* __restrict__ out_ext, int fused) {

    extern __shared__ float sm[];
    const uint32_t smb = smem_u32(sm);
    const int tid = threadIdx.x;
    const int lane = tid & 31, wid = tid >> 5;
    const int gid = lane >> 2, tg = lane & 3;
    const int rbw = wid & 3;       // warp m-block (32 rows)
    const int nbl = wid >> 2;      // warp n-block (32 cols) within CTA
    const int nbp = fused ? (blockIdx.x >> 2) : blockIdx.x;
    const int zz  = fused ? (blockIdx.x & 3) : 4;
    const int by  = blockIdx.y;

    const float* Af = fused ? g_mnf : g_of;
    const float2* Bw = g_wf + (size_t)zz * 32768;

    float acc[2][4][4];
#pragma unroll
    for (int mt = 0; mt < 2; mt++)
#pragma unroll
        for (int nt = 0; nt < 4; nt++)
#pragma unroll
            for (int j = 0; j < 4; j++) acc[mt][nt][j] = 0.f;

    stage_tile(smb, 0, 0, by, nbp, tid, Af, Bw);
    asm volatile("cp.async.commit_group;" ::: "memory");
    stage_tile(smb, 1, 1, by, nbp, tid, Af, Bw);
    asm volatile("cp.async.commit_group;" ::: "memory");

    int cur = 0, nxt = 2;
#pragma unroll 1
    for (int kt = 0; kt < 8; kt++) {
        asm volatile("cp.async.wait_group 1;" ::: "memory");
        __syncthreads();
        if (kt < 6) stage_tile(smb, nxt, kt + 2, by, nbp, tid, Af, Bw);
        asm volatile("cp.async.commit_group;" ::: "memory");

        const float* As = sm + cur * STAGE_F;
        const float* Bs = As + ASTAGE_F;
#pragma unroll
        for (int kc = 0; kc < 4; kc++) {
            float4 va0 = *(const float4*)&As[(rbw * 4 + kc) * 256 + lane * 4];
            float4 va1 = *(const float4*)&As[(rbw * 4 + kc) * 256 + 128 + lane * 4];
            uint32_t a0[4] = {__float_as_uint(va0.x), __float_as_uint(va0.y),
                              __float_as_uint(va0.z), __float_as_uint(va0.w)};
            uint32_t a1[4] = {__float_as_uint(va1.x), __float_as_uint(va1.y),
                              __float_as_uint(va1.z), __float_as_uint(va1.w)};
#pragma unroll
            for (int nt = 0; nt < 4; nt++) {
                float2 vb = *(const float2*)&Bs[nbl * 1024 + ((kc * 4 + nt) * 32 + lane) * 2];
                uint32_t b[2] = {__float_as_uint(vb.x), __float_as_uint(vb.y)};
                MMA4(acc[0][nt], a0, b);
                MMA4(acc[1][nt], a1, b);
            }
        }
        cur = (cur == 2) ? 0 : cur + 1;
        nxt = (nxt == 2) ? 0 : nxt + 1;
    }

    // ---- epilogue ----
#pragma unroll
    for (int mt = 0; mt < 2; mt++) {
#pragma unroll
        for (int nt = 0; nt < 4; nt++) {
#pragma unroll
            for (int half = 0; half < 2; half++) {
                int gr = by * 128 + rbw * 32 + mt * 16 + gid + half * 8;
                int gc = nbp * 64 + nbl * 32 + nt * 8 + tg * 2;
                float2 val;
                val.x = acc[mt][nt][half * 2 + 0];
                val.y = acc[mt][nt][half * 2 + 1];
                if (fused && zz == 3) {
                    val.x = 1.f / (1.f + __expf(-(val.x + bias_g[gc + 0])));
                    val.y = 1.f / (1.f + __expf(-(val.y + bias_g[gc + 1])));
                    *(float2*)(g_gate + (size_t)gr * 256 + gc) = val;
                } else if (!fused) {
                    val.x += bias_o[gc + 0];
                    val.y += bias_o[gc + 1];
                    *(float2*)(out_ext + (size_t)gr * 256 + gc) = val;
                } else {
                    int s = gr >> 8, r = gr & 255, h = gc >> 5, c = gc & 31;
                    float* out = (zz == 0) ? g_q : (zz == 1) ? g_k : g_v;
                    *(float2*)(out + (((size_t)(s * NH + h) * R_RES + r) * CH + c)) = val;
                }
            }
        }
    }
}

// ---------------- tensor-core flash attention; epilogue fuses gating + frag store --------
__global__ void __launch_bounds__(256, 2) attn_mma_kernel() {
    const int sh = blockIdx.y;
    const int s = sh >> 3, h = sh & 7;
    const int qb = blockIdx.x;
    const int tid = threadIdx.x;
    const int lane = tid & 31, wid = tid >> 5;
    const int gid = lane >> 2, tg = lane & 3;
    const int wrow = wid * 16;

    __shared__ __align__(16) float Qs[128 * 36];
    __shared__ __align__(16) float Ks[64 * 36];
    __shared__ __align__(16) float Vs[64 * 40];

    const float* qg = g_q + ((size_t)sh * R_RES + qb * 128) * CH;
#pragma unroll
    for (int it = 0; it < 4; it++) {
        int i = tid + it * 256;
        int r = i >> 3, c4 = i & 7;
        float4 v = ((const float4*)qg)[i];
        v.x = ftf32(v.x); v.y = ftf32(v.y); v.z = ftf32(v.z); v.w = ftf32(v.w);
        *(float4*)&Qs[r * 36 + c4 * 4] = v;
    }
    __syncthreads();

    uint32_t qa[4][4];
#pragma unroll
    for (int ks = 0; ks < 4; ks++) {
        int r0 = wrow + gid;
        qa[ks][0] = __float_as_uint(Qs[r0 * 36 + ks * 8 + tg]);
        qa[ks][1] = __float_as_uint(Qs[(r0 + 8) * 36 + ks * 8 + tg]);
        qa[ks][2] = __float_as_uint(Qs[r0 * 36 + ks * 8 + tg + 4]);
        qa[ks][3] = __float_as_uint(Qs[(r0 + 8) * 36 + ks * 8 + tg + 4]);
    }

    float m_i[2] = {-3.0e38f, -3.0e38f};
    float l_i[2] = {0.f, 0.f};
    float accO[4][4];
#pragma unroll
    for (int ct = 0; ct < 4; ct++)
#pragma unroll
        for (int j = 0; j < 4; j++) accO[ct][j] = 0.f;

    const float scale = 0.17677669529663687f;
    const float* bias_r0 = g_bias + ((size_t)h * R_RES + qb * 128 + wrow + gid) * R_RES;
    const float* bias_r1 = bias_r0 + 8 * R_RES;

    for (int kt = 0; kt < 4; kt++) {
        const float* kg = g_k + ((size_t)sh * R_RES + kt * 64) * CH;
        const float* vg = g_v + ((size_t)sh * R_RES + kt * 64) * CH;
#pragma unroll
        for (int it = 0; it < 2; it++) {
            int i = tid + it * 256;
            int r = i >> 3, c4 = i & 7;
            float4 kv = ((const float4*)kg)[i];
            kv.x = ftf32(kv.x); kv.y = ftf32(kv.y); kv.z = ftf32(kv.z); kv.w = ftf32(kv.w);
            *(float4*)&Ks[r * 36 + c4 * 4] = kv;
            float4 vv = ((const float4*)vg)[i];
            vv.x = ftf32(vv.x); vv.y = ftf32(vv.y); vv.z = ftf32(vv.z); vv.w = ftf32(vv.w);
            *(float4*)&Vs[r * 40 + c4 * 4] = vv;
        }
        __syncthreads();

        float acc[8][4];
#pragma unroll
        for (int nt = 0; nt < 8; nt++)
#pragma unroll
            for (int j = 0; j < 4; j++) acc[nt][j] = 0.f;

#pragma unroll
        for (int nt = 0; nt < 8; nt++) {
            const float* kr = &Ks[(nt * 8 + gid) * 36 + tg];
            uint32_t b[2];
#pragma unroll
            for (int ks = 0; ks < 4; ks++) {
                b[0] = __float_as_uint(kr[ks * 8]);
                b[1] = __float_as_uint(kr[ks * 8 + 4]);
                MMA4(acc[nt], qa[ks], b);
            }
        }

        float2 bb0[8], bb1[8];
#pragma unroll
        for (int nt = 0; nt < 8; nt++) {
            int col = kt * 64 + nt * 8 + 2 * tg;
            bb0[nt] = *(const float2*)&bias_r0[col];
            bb1[nt] = *(const float2*)&bias_r1[col];
        }
#pragma unroll
        for (int nt = 0; nt < 8; nt++) {
            acc[nt][0] = fmaf(acc[nt][0], scale, bb0[nt].x);
            acc[nt][1] = fmaf(acc[nt][1], scale, bb0[nt].y);
            acc[nt][2] = fmaf(acc[nt][2], scale, bb1[nt].x);
            acc[nt][3] = fmaf(acc[nt][3], scale, bb1[nt].y);
        }

        float mt[2] = {-3.0e38f, -3.0e38f};
#pragma unroll
        for (int nt = 0; nt < 8; nt++) {
            mt[0] = fmaxf(mt[0], fmaxf(acc[nt][0], acc[nt][1]));
            mt[1] = fmaxf(mt[1], fmaxf(acc[nt][2], acc[nt][3]));
        }
#pragma unroll
        for (int rh = 0; rh < 2; rh++) {
            mt[rh] = fmaxf(mt[rh], __shfl_xor_sync(0xffffffff, mt[rh], 1));
            mt[rh] = fmaxf(mt[rh], __shfl_xor_sync(0xffffffff, mt[rh], 2));
            float mnew = fmaxf(m_i[rh], mt[rh]);
            float corr = __expf(m_i[rh] - mnew);
            m_i[rh] = mnew;
            l_i[rh] *= corr;
#pragma unroll
            for (int ct = 0; ct < 4; ct++) {
                accO[ct][rh * 2 + 0] *= corr;
                accO[ct][rh * 2 + 1] *= corr;
            }
        }
#pragma unroll
        for (int nt = 0; nt < 8; nt++) {
            acc[nt][0] = __expf(acc[nt][0] - m_i[0]);
            acc[nt][1] = __expf(acc[nt][1] - m_i[0]);
            acc[nt][2] = __expf(acc[nt][2] - m_i[1]);
            acc[nt][3] = __expf(acc[nt][3] - m_i[1]);
            l_i[0] += acc[nt][0] + acc[nt][1];
            l_i[1] += acc[nt][2] + acc[nt][3];
        }

        const int src = 4 * gid + (tg >> 1);
        const bool odd = tg & 1;
#pragma unroll
        for (int nt = 0; nt < 8; nt++) {
            float v0  = __shfl_sync(0xffffffff, acc[nt][0], src);
            float v1  = __shfl_sync(0xffffffff, acc[nt][1], src);
            float w0  = __shfl_sync(0xffffffff, acc[nt][2], src);
            float w1  = __shfl_sync(0xffffffff, acc[nt][3], src);
            float v0b = __shfl_sync(0xffffffff, acc[nt][0], src + 2);
            float v1b = __shfl_sync(0xffffffff, acc[nt][1], src + 2);
            float w0b = __shfl_sync(0xffffffff, acc[nt][2], src + 2);
            float w1b = __shfl_sync(0xffffffff, acc[nt][3], src + 2);
            uint32_t pa[4];
            pa[0] = ftf32u(odd ? v1 : v0);
            pa[1] = ftf32u(odd ? w1 : w0);
            pa[2] = ftf32u(odd ? v1b : v0b);
            pa[3] = ftf32u(odd ? w1b : w0b);
            const float* vr = &Vs[(nt * 8 + tg) * 40 + gid];
            uint32_t b[2];
#pragma unroll
            for (int ct = 0; ct < 4; ct++) {
                b[0] = __float_as_uint(vr[ct * 8]);
                b[1] = __float_as_uint(vr[ct * 8 + 160]);
                MMA4(accO[ct], pa, b);
            }
        }
        __syncthreads();
    }

    float inv[2];
#pragma unroll
    for (int rh = 0; rh < 2; rh++) {
        float l = l_i[rh];
        l += __shfl_xor_sync(0xffffffff, l, 1);
        l += __shfl_xor_sync(0xffffffff, l, 2);
        inv[rh] = 1.0f / l;
    }
    // epilogue: multiply by gate, tf32-round, scatter into fragment-ordered g_of
#pragma unroll
    for (int ct = 0; ct < 4; ct++) {
#pragma unroll
        for (int rh = 0; rh < 2; rh++) {
            int r = qb * 128 + wrow + gid + rh * 8;
            int grow = s * R_RES + r;
            int col = h * CH + ct * 8 + 2 * tg;
            float2 gt = *(const float2*)&g_gate[(size_t)grow * 256 + col];
            float vx = ftf32(accO[ct][rh * 2 + 0] * inv[rh] * gt.x);
            float vy = ftf32(accO[ct][rh * 2 + 1] * inv[rh] * gt.y);
            int rr = grow & 31;
            int mt2 = rr >> 4, sub2 = (rr >> 3) & 1, gid2 = rr & 7;
            int kc2 = col >> 3, half2 = (col >> 2) & 1;
            size_t base = ((size_t)(grow >> 5) * 32 + kc2) * 256 + mt2 * 128 + sub2 + 2 * half2;
            g_of[base + (gid2 * 4 + (col & 3)) * 4] = vx;
            g_of[base + (gid2 * 4 + ((col + 1) & 3)) * 4] = vy;
        }
    }
}

// ---------------- launch ----------------
extern "C" void kernel_launch(void* const* d_in, const int* in_sizes, int n_in,
                              void* d_out, int out_size) {
    (void)in_sizes; (void)n_in; (void)out_size;
    const float* m   = (const float*)d_in[0];
    const float* z   = (const float*)d_in[1];
    const float* lmw = (const float*)d_in[2];
    const float* lmb = (const float*)d_in[3];
    const float* lzw = (const float*)d_in[4];
    const float* lzb = (const float*)d_in[5];
    const float* Wz  = (const float*)d_in[6];
    const float* Wq  = (const float*)d_in[7];
    const float* Wk  = (const float*)d_in[8];
    const float* Wv  = (const float*)d_in[9];
    const float* Wg  = (const float*)d_in[10];
    const float* bg  = (const float*)d_in[11];
    const float* Wo  = (const float*)d_in[12];
    const float* bo  = (const float*)d_in[13];

    cudaFuncSetAttribute(tf32gemm_kernel, cudaFuncAttributeMaxDynamicSharedMemorySize, SM_BYTES);

    ln_m_kernel<<<2048, 256>>>(m, lmw, lmb);
    ln_z_bias_kernel<<<8192, 256>>>(z, lzw, lzb, Wz);
    repack_kernel<<<640, 256>>>(Wq, Wk, Wv, Wg, Wo);

    tf32gemm_kernel<<<dim3(16, 512), 256, SM_BYTES>>>(bg, nullptr, nullptr, 1);

    attn_mma_kernel<<<dim3(2, S_SEQ * NH), 256>>>();

    tf32gemm_kernel<<<dim3(4, 512), 256, SM_BYTES>>>(nullptr, bo, (float*)d_out, 0);
}

// round 7
// speedup vs baseline: 1.5288x; 1.5288x over previous
#include <cuda_runtime.h>
#include <math.h>
#include <stdint.h>

#define S_SEQ 256
#define R_RES 256
#define CM 256
#define CZ 128
#define NH 8
#define CH 32
#define HC 256
#define LNEPS 1e-5f

// ---------------- scratch (device globals; no allocation allowed) ----------------
// fragment layout for a 32-row x 8-col chunk (rb = row/32, kc = col/8):
//   offset = (rb*32 + kc)*256 + mt*128 + lane*4 + f
//   row = rb*32 + mt*16 + sub*8 + (lane>>2), col = kc*8 + half*4 + (lane&3), f = sub + 2*half
__device__ float g_mnf[(size_t)S_SEQ * R_RES * CM];      // 64 MB  LN(m), tf32, frag layout
__device__ float g_q[(size_t)S_SEQ * R_RES * HC];        // 64 MB  flat (s, r, h*32+c)
__device__ float g_k[(size_t)S_SEQ * R_RES * HC];        // 64 MB
__device__ float g_v[(size_t)S_SEQ * R_RES * HC];        // 64 MB
__device__ float g_gate[(size_t)S_SEQ * R_RES * HC];     // 64 MB  sigmoid(mn@Wg+bg)
__device__ float g_of[(size_t)S_SEQ * R_RES * HC];       // 64 MB  gate .* attn_out, tf32, frag layout
__device__ float g_bias[(size_t)NH * R_RES * R_RES];     //  2 MB  [h][q][k]
__device__ float4 g_wf4[5 * 16384];                      //  2.5 MB B frags [z][kt][nb][ks][ntp][lane]

__device__ __forceinline__ float ftf32(float x) {
    uint32_t u;
    asm("cvt.rna.tf32.f32 %0, %1;" : "=r"(u) : "f"(x));
    return __uint_as_float(u);
}
__device__ __forceinline__ uint32_t ftf32u(float x) {
    uint32_t u;
    asm("cvt.rna.tf32.f32 %0, %1;" : "=r"(u) : "f"(x));
    return u;
}
__device__ __forceinline__ uint32_t smem_u32(const void* p) {
    uint32_t a;
    asm("{ .reg .u64 t; cvta.to.shared.u64 t, %1; cvt.u32.u64 %0, t; }" : "=r"(a) : "l"(p));
    return a;
}
__device__ __forceinline__ void cp16(uint32_t dst, const void* src) {
    asm volatile("cp.async.cg.shared.global [%0], [%1], 16;" :: "r"(dst), "l"(src));
}

#define MMA4(d, a, b)                                                              \
    asm volatile("mma.sync.aligned.m16n8k8.row.col.f32.tf32.tf32.f32 "             \
                 "{%0,%1,%2,%3},{%4,%5,%6,%7},{%8,%9},{%0,%1,%2,%3};"              \
                 : "+f"(d[0]), "+f"(d[1]), "+f"(d[2]), "+f"(d[3])                  \
                 : "r"(a[0]), "r"(a[1]), "r"(a[2]), "r"(a[3]), "r"(b[0]), "r"(b[1]))

// ---------------- LayerNorm m -> fragment-ordered tf32 g_mnf ----------------
__global__ void __launch_bounds__(256) ln_m_kernel(const float* __restrict__ x,
                                                   const float* __restrict__ w,
                                                   const float* __restrict__ b) {
    __shared__ float sln[32 * 260];
    const int tid = threadIdx.x;
    const int wid = tid >> 5, lane = tid & 31;

    const float4 w0 = *(const float4*)(w + lane * 8);
    const float4 w1 = *(const float4*)(w + lane * 8 + 4);
    const float4 b0 = *(const float4*)(b + lane * 8);
    const float4 b1 = *(const float4*)(b + lane * 8 + 4);

#pragma unroll 1
    for (int q = 0; q < 4; q++) {
        int lr = wid * 4 + q;
        size_t row = (size_t)blockIdx.x * 32 + lr;
        const float* xp = x + row * CM + lane * 8;
        float4 v0 = *(const float4*)xp;
        float4 v1 = *(const float4*)(xp + 4);
        float s  = v0.x + v0.y + v0.z + v0.w + v1.x + v1.y + v1.z + v1.w;
        float sq = v0.x * v0.x + v0.y * v0.y + v0.z * v0.z + v0.w * v0.w
                 + v1.x * v1.x + v1.y * v1.y + v1.z * v1.z + v1.w * v1.w;
#pragma unroll
        for (int st = 16; st > 0; st >>= 1) {
            s  += __shfl_xor_sync(0xffffffff, s, st);
            sq += __shfl_xor_sync(0xffffffff, sq, st);
        }
        float mean = s * (1.0f / CM);
        float inv  = rsqrtf(sq * (1.0f / CM) - mean * mean + LNEPS);
        float* sp = &sln[lr * 260 + lane * 8];
        sp[0] = ftf32((v0.x - mean) * inv * w0.x + b0.x);
        sp[1] = ftf32((v0.y - mean) * inv * w0.y + b0.y);
        sp[2] = ftf32((v0.z - mean) * inv * w0.z + b0.z);
        sp[3] = ftf32((v0.w - mean) * inv * w0.w + b0.w);
        sp[4] = ftf32((v1.x - mean) * inv * w1.x + b1.x);
        sp[5] = ftf32((v1.y - mean) * inv * w1.y + b1.y);
        sp[6] = ftf32((v1.z - mean) * inv * w1.z + b1.z);
        sp[7] = ftf32((v1.w - mean) * inv * w1.w + b1.w);
    }
    __syncthreads();

    float* dst = g_mnf + (size_t)blockIdx.x * 8192;
#pragma unroll
    for (int it = 0; it < 8; it++) {
        int i = tid + it * 256;
        int f = i * 4;
        int kc = f >> 8, rem = f & 255;
        int mt = rem >> 7, lp = (rem >> 2) & 31;
        int gid2 = lp >> 2, tg2 = lp & 3;
        int cb = kc * 8 + tg2;
        float4 v;
        v.x = sln[(mt * 16 + 0 + gid2) * 260 + cb];
        v.y = sln[(mt * 16 + 8 + gid2) * 260 + cb];
        v.z = sln[(mt * 16 + 0 + gid2) * 260 + cb + 4];
        v.w = sln[(mt * 16 + 8 + gid2) * 260 + cb + 4];
        *(float4*)(dst + f) = v;
    }
}

// ---------------- LN(z) + pair-bias: one warp per (q,k) ----------------
__global__ void __launch_bounds__(256) ln_z_bias_kernel(
    const float* __restrict__ z, const float* __restrict__ w,
    const float* __restrict__ b, const float* __restrict__ Wz) {
    __shared__ float sWzT[8 * 128];
    const int tid = threadIdx.x;
    for (int i = tid; i < 1024; i += 256) {
        int zz = i >> 3, h = i & 7;
        sWzT[h * 128 + zz] = Wz[i];
    }
    __syncthreads();

    const int wid = tid >> 5, lane = tid & 31;
    const int qk = blockIdx.x * 8 + wid;
    const int q = qk >> 8, k = qk & 255;
    float4 v = *(const float4*)(z + (size_t)qk * CZ + 4 * lane);
    float s  = v.x + v.y + v.z + v.w;
    float sq = v.x * v.x + v.y * v.y + v.z * v.z + v.w * v.w;
#pragma unroll
    for (int st = 16; st > 0; st >>= 1) {
        s  += __shfl_xor_sync(0xffffffff, s, st);
        sq += __shfl_xor_sync(0xffffffff, sq, st);
    }
    float mean = s * (1.0f / CZ);
    float inv  = rsqrtf(sq * (1.0f / CZ) - mean * mean + LNEPS);
    float4 w4 = *(const float4*)(w + 4 * lane);
    float4 b4 = *(const float4*)(b + 4 * lane);
    float4 zn;
    zn.x = (v.x - mean) * inv * w4.x + b4.x;
    zn.y = (v.y - mean) * inv * w4.y + b4.y;
    zn.z = (v.z - mean) * inv * w4.z + b4.z;
    zn.w = (v.w - mean) * inv * w4.w + b4.w;

    float p[8];
#pragma unroll
    for (int h = 0; h < 8; h++) {
        float4 wz = *(const float4*)&sWzT[h * 128 + 4 * lane];
        p[h] = zn.x * wz.x + zn.y * wz.y + zn.z * wz.z + zn.w * wz.w;
    }
#pragma unroll
    for (int st = 16; st > 0; st >>= 1) {
#pragma unroll
        for (int h = 0; h < 8; h++) p[h] += __shfl_xor_sync(0xffffffff, p[h], st);
    }
    float outv = p[0];
#pragma unroll
    for (int h = 1; h < 8; h++) if (lane == h) outv = p[h];
    if (lane < 8)
        g_bias[((size_t)lane * R_RES + q) * R_RES + k] = outv;
}

// ---------------- B-fragment repack: [zz][kt][nb][ks][ntp][lane] float4 ----------------
// float4 = {ntA(k), ntA(k+4), ntB(k), ntB(k+4)} with ntA=2*ntp, ntB=2*ntp+1
__global__ void __launch_bounds__(256) repack_kernel(
    const float* __restrict__ w0, const float* __restrict__ w1,
    const float* __restrict__ w2, const float* __restrict__ w3,
    const float* __restrict__ w4) {
    int t = blockIdx.x * 256 + threadIdx.x;       // < 81920
    int lane = t & 31;
    int ntp = (t >> 5) & 1;
    int ks = (t >> 6) & 3;
    int nb = (t >> 8) & 7;
    int kt = (t >> 11) & 7;
    int zz = t >> 14;
    const float* W = (zz == 0) ? w0 : (zz == 1) ? w1 : (zz == 2) ? w2 : (zz == 3) ? w3 : w4;
    int krow = kt * 32 + ks * 8 + (lane & 3);
    int gid = lane >> 2;
    int ncolA = nb * 32 + (2 * ntp) * 8 + gid;
    int ncolB = ncolA + 8;
    float4 v;
    v.x = ftf32(W[krow * 256 + ncolA]);
    v.y = ftf32(W[(krow + 4) * 256 + ncolA]);
    v.z = ftf32(W[krow * 256 + ncolB]);
    v.w = ftf32(W[(krow + 4) * 256 + ncolB]);
    g_wf4[t] = v;
}

// ---------------- cp.async-pipelined tf32 GEMM: C(65536x256) = A @ W ----------------
// fused==1: blockIdx.x = nbp*4+z; z=0/1/2 -> q/k/v (flat), z=3 -> gate (sigmoid+bg)
// fused==0: A = g_of (frag layout), out = d_out + bo
#define ASTAGE_F 4096
#define STAGE_F  6144
#define SM_BYTES (3 * STAGE_F * 4)   // 73728

__device__ __forceinline__ void stage_tile(uint32_t smb, int buf, int kt, int by, int nbp,
                                           int tid, const float* Af, const float4* Bw) {
    uint32_t db = smb + (uint32_t)buf * (STAGE_F * 4);
#pragma unroll
    for (int it = 0; it < 4; it++) {
        int ca = tid + it * 256;
        int rb = ca >> 8, kc = (ca >> 6) & 3, c = ca & 63;
        const float* s = Af + ((size_t)(by * 128 + rb * 32 + kt * 4 + kc)) * 256 + c * 4;
        cp16(db + (uint32_t)(((rb * 4 + kc) * 256 + c * 4) * 4), s);
    }
#pragma unroll
    for (int it = 0; it < 2; it++) {
        int cb = tid + it * 256;                       // 512 float4 per tile
        int nl = cb >> 8, inner = cb & 255;
        const float4* s = Bw + ((size_t)(kt * 8 + nbp * 2 + nl)) * 256 + inner;
        cp16(db + (uint32_t)((ASTAGE_F + nl * 1024 + inner * 4) * 4), s);
    }
}

__global__ void __launch_bounds__(256, 2) tf32gemm_kernel(
    const float* __restrict__ bias_g, const float* __restrict__ bias_o,
    float* __restrict__ out_ext, int fused) {

    extern __shared__ float sm[];
    const uint32_t smb = smem_u32(sm);
    const int tid = threadIdx.x;
    const int lane = tid & 31, wid = tid >> 5;
    const int gid = lane >> 2, tg = lane & 3;
    const int rbw = wid & 3;       // warp m-block (32 rows)
    const int nbl = wid >> 2;      // warp n-block (32 cols)
    const int nbp = fused ? (blockIdx.x >> 2) : blockIdx.x;
    const int zz  = fused ? (blockIdx.x & 3) : 4;
    const int by  = blockIdx.y;

    const float* Af = fused ? g_mnf : g_of;
    const float4* Bw = g_wf4 + (size_t)zz * 16384;

    float acc[2][4][4];
#pragma unroll
    for (int mt = 0; mt < 2; mt++)
#pragma unroll
        for (int nt = 0; nt < 4; nt++)
#pragma unroll
            for (int j = 0; j < 4; j++) acc[mt][nt][j] = 0.f;

    stage_tile(smb, 0, 0, by, nbp, tid, Af, Bw);
    asm volatile("cp.async.commit_group;" ::: "memory");
    stage_tile(smb, 1, 1, by, nbp, tid, Af, Bw);
    asm volatile("cp.async.commit_group;" ::: "memory");

    int cur = 0, nxt = 2;
#pragma unroll 1
    for (int kt = 0; kt < 8; kt++) {
        asm volatile("cp.async.wait_group 1;" ::: "memory");
        __syncthreads();
        if (kt < 6) stage_tile(smb, nxt, kt + 2, by, nbp, tid, Af, Bw);
        asm volatile("cp.async.commit_group;" ::: "memory");

        const float* As = sm + cur * STAGE_F;
        const float* Bs = As + ASTAGE_F;
#pragma unroll
        for (int kc = 0; kc < 4; kc++) {
            float4 va0 = *(const float4*)&As[(rbw * 4 + kc) * 256 + lane * 4];
            float4 va1 = *(const float4*)&As[(rbw * 4 + kc) * 256 + 128 + lane * 4];
            uint32_t a0[4] = {__float_as_uint(va0.x), __float_as_uint(va0.y),
                              __float_as_uint(va0.z), __float_as_uint(va0.w)};
            uint32_t a1[4] = {__float_as_uint(va1.x), __float_as_uint(va1.y),
                              __float_as_uint(va1.z), __float_as_uint(va1.w)};
#pragma unroll
            for (int ntp = 0; ntp < 2; ntp++) {
                float4 vb = *(const float4*)&Bs[nbl * 1024 + ((kc * 2 + ntp) * 32 + lane) * 4];
                uint32_t b0[2] = {__float_as_uint(vb.x), __float_as_uint(vb.y)};
                uint32_t b1[2] = {__float_as_uint(vb.z), __float_as_uint(vb.w)};
                MMA4(acc[0][2 * ntp], a0, b0);
                MMA4(acc[1][2 * ntp], a1, b0);
                MMA4(acc[0][2 * ntp + 1], a0, b1);
                MMA4(acc[1][2 * ntp + 1], a1, b1);
            }
        }
        cur = (cur == 2) ? 0 : cur + 1;
        nxt = (nxt == 2) ? 0 : nxt + 1;
    }

    // ---- epilogue (flat, coalesced float2 everywhere) ----
    float* out = (!fused) ? out_ext
               : (zz == 0) ? g_q : (zz == 1) ? g_k : (zz == 2) ? g_v : g_gate;
#pragma unroll
    for (int mt = 0; mt < 2; mt++) {
#pragma unroll
        for (int nt = 0; nt < 4; nt++) {
#pragma unroll
            for (int half = 0; half < 2; half++) {
                int gr = by * 128 + rbw * 32 + mt * 16 + gid + half * 8;
                int gc = nbp * 64 + nbl * 32 + nt * 8 + tg * 2;
                float2 val;
                val.x = acc[mt][nt][half * 2 + 0];
                val.y = acc[mt][nt][half * 2 + 1];
                if (fused && zz == 3) {
                    val.x = 1.f / (1.f + __expf(-(val.x + bias_g[gc + 0])));
                    val.y = 1.f / (1.f + __expf(-(val.y + bias_g[gc + 1])));
                } else if (!fused) {
                    val.x += bias_o[gc + 0];
                    val.y += bias_o[gc + 1];
                }
                *(float2*)(out + (size_t)gr * 256 + gc) = val;
            }
        }
    }
}

// ---------------- tensor-core flash attention; gated, frag-ordered coalesced output ------
__global__ void __launch_bounds__(256, 2) attn_mma_kernel() {
    const int sh = blockIdx.y;
    const int s = sh >> 3, h = sh & 7;
    const int qb = blockIdx.x;
    const int tid = threadIdx.x;
    const int lane = tid & 31, wid = tid >> 5;
    const int gid = lane >> 2, tg = lane & 3;
    const int wrow = wid * 16;

    __shared__ __align__(16) float Qs[128 * 36];   // reused for output staging
    __shared__ __align__(16) float Ks[64 * 36];
    __shared__ __align__(16) float Vs[64 * 40];

    // flat Q: rows qb*128.., cols h*32..h*32+31, row stride 256
    const float* qg = g_q + ((size_t)(s * R_RES + qb * 128)) * HC + h * CH;
#pragma unroll
    for (int it = 0; it < 4; it++) {
        int i = tid + it * 256;
        int r = i >> 3, c4 = i & 7;
        float4 v = *(const float4*)(qg + (size_t)r * HC + c4 * 4);
        v.x = ftf32(v.x); v.y = ftf32(v.y); v.z = ftf32(v.z); v.w = ftf32(v.w);
        *(float4*)&Qs[r * 36 + c4 * 4] = v;
    }
    __syncthreads();

    uint32_t qa[4][4];
#pragma unroll
    for (int ks = 0; ks < 4; ks++) {
        int r0 = wrow + gid;
        qa[ks][0] = __float_as_uint(Qs[r0 * 36 + ks * 8 + tg]);
        qa[ks][1] = __float_as_uint(Qs[(r0 + 8) * 36 + ks * 8 + tg]);
        qa[ks][2] = __float_as_uint(Qs[r0 * 36 + ks * 8 + tg + 4]);
        qa[ks][3] = __float_as_uint(Qs[(r0 + 8) * 36 + ks * 8 + tg + 4]);
    }

    float m_i[2] = {-3.0e38f, -3.0e38f};
    float l_i[2] = {0.f, 0.f};
    float accO[4][4];
#pragma unroll
    for (int ct = 0; ct < 4; ct++)
#pragma unroll
        for (int j = 0; j < 4; j++) accO[ct][j] = 0.f;

    const float scale = 0.17677669529663687f;
    const float* bias_r0 = g_bias + ((size_t)h * R_RES + qb * 128 + wrow + gid) * R_RES;
    const float* bias_r1 = bias_r0 + 8 * R_RES;

    for (int kt = 0; kt < 4; kt++) {
        const float* kg = g_k + ((size_t)(s * R_RES + kt * 64)) * HC + h * CH;
        const float* vg = g_v + ((size_t)(s * R_RES + kt * 64)) * HC + h * CH;
#pragma unroll
        for (int it = 0; it < 2; it++) {
            int i = tid + it * 256;
            int r = i >> 3, c4 = i & 7;
            float4 kv = *(const float4*)(kg + (size_t)r * HC + c4 * 4);
            kv.x = ftf32(kv.x); kv.y = ftf32(kv.y); kv.z = ftf32(kv.z); kv.w = ftf32(kv.w);
            *(float4*)&Ks[r * 36 + c4 * 4] = kv;
            float4 vv = *(const float4*)(vg + (size_t)r * HC + c4 * 4);
            vv.x = ftf32(vv.x); vv.y = ftf32(vv.y); vv.z = ftf32(vv.z); vv.w = ftf32(vv.w);
            *(float4*)&Vs[r * 40 + c4 * 4] = vv;
        }
        __syncthreads();

        float acc[8][4];
#pragma unroll
        for (int nt = 0; nt < 8; nt++)
#pragma unroll
            for (int j = 0; j < 4; j++) acc[nt][j] = 0.f;

#pragma unroll
        for (int nt = 0; nt < 8; nt++) {
            const float* kr = &Ks[(nt * 8 + gid) * 36 + tg];
            uint32_t b[2];
#pragma unroll
            for (int ks = 0; ks < 4; ks++) {
                b[0] = __float_as_uint(kr[ks * 8]);
                b[1] = __float_as_uint(kr[ks * 8 + 4]);
                MMA4(acc[nt], qa[ks], b);
            }
        }

        float2 bb0[8], bb1[8];
#pragma unroll
        for (int nt = 0; nt < 8; nt++) {
            int col = kt * 64 + nt * 8 + 2 * tg;
            bb0[nt] = *(const float2*)&bias_r0[col];
            bb1[nt] = *(const float2*)&bias_r1[col];
        }
#pragma unroll
        for (int nt = 0; nt < 8; nt++) {
            acc[nt][0] = fmaf(acc[nt][0], scale, bb0[nt].x);
            acc[nt][1] = fmaf(acc[nt][1], scale, bb0[nt].y);
            acc[nt][2] = fmaf(acc[nt][2], scale, bb1[nt].x);
            acc[nt][3] = fmaf(acc[nt][3], scale, bb1[nt].y);
        }

        float mt[2] = {-3.0e38f, -3.0e38f};
#pragma unroll
        for (int nt = 0; nt < 8; nt++) {
            mt[0] = fmaxf(mt[0], fmaxf(acc[nt][0], acc[nt][1]));
            mt[1] = fmaxf(mt[1], fmaxf(acc[nt][2], acc[nt][3]));
        }
#pragma unroll
        for (int rh = 0; rh < 2; rh++) {
            mt[rh] = fmaxf(mt[rh], __shfl_xor_sync(0xffffffff, mt[rh], 1));
            mt[rh] = fmaxf(mt[rh], __shfl_xor_sync(0xffffffff, mt[rh], 2));
            float mnew = fmaxf(m_i[rh], mt[rh]);
            float corr = __expf(m_i[rh] - mnew);
            m_i[rh] = mnew;
            l_i[rh] *= corr;
#pragma unroll
            for (int ct = 0; ct < 4; ct++) {
                accO[ct][rh * 2 + 0] *= corr;
                accO[ct][rh * 2 + 1] *= corr;
            }
        }
#pragma unroll
        for (int nt = 0; nt < 8; nt++) {
            acc[nt][0] = __expf(acc[nt][0] - m_i[0]);
            acc[nt][1] = __expf(acc[nt][1] - m_i[0]);
            acc[nt][2] = __expf(acc[nt][2] - m_i[1]);
            acc[nt][3] = __expf(acc[nt][3] - m_i[1]);
            l_i[0] += acc[nt][0] + acc[nt][1];
            l_i[1] += acc[nt][2] + acc[nt][3];
        }

        const int src = 4 * gid + (tg >> 1);
        const bool odd = tg & 1;
#pragma unroll
        for (int nt = 0; nt < 8; nt++) {
            float v0  = __shfl_sync(0xffffffff, acc[nt][0], src);
            float v1  = __shfl_sync(0xffffffff, acc[nt][1], src);
            float w0  = __shfl_sync(0xffffffff, acc[nt][2], src);
            float w1  = __shfl_sync(0xffffffff, acc[nt][3], src);
            float v0b = __shfl_sync(0xffffffff, acc[nt][0], src + 2);
            float v1b = __shfl_sync(0xffffffff, acc[nt][1], src + 2);
            float w0b = __shfl_sync(0xffffffff, acc[nt][2], src + 2);
            float w1b = __shfl_sync(0xffffffff, acc[nt][3], src + 2);
            uint32_t pa[4];
            pa[0] = ftf32u(odd ? v1 : v0);
            pa[1] = ftf32u(odd ? w1 : w0);
            pa[2] = ftf32u(odd ? v1b : v0b);
            pa[3] = ftf32u(odd ? w1b : w0b);
            const float* vr = &Vs[(nt * 8 + tg) * 40 + gid];
            uint32_t b[2];
#pragma unroll
            for (int ct = 0; ct < 4; ct++) {
                b[0] = __float_as_uint(vr[ct * 8]);
                b[1] = __float_as_uint(vr[ct * 8 + 160]);
                MMA4(accO[ct], pa, b);
            }
        }
        __syncthreads();
    }

    float inv[2];
#pragma unroll
    for (int rh = 0; rh < 2; rh++) {
        float l = l_i[rh];
        l += __shfl_xor_sync(0xffffffff, l, 1);
        l += __shfl_xor_sync(0xffffffff, l, 2);
        inv[rh] = 1.0f / l;
    }

    // stage gated output into smem (local layout 128 x 32, stride 36)
#pragma unroll
    for (int ct = 0; ct < 4; ct++) {
#pragma unroll
        for (int rh = 0; rh < 2; rh++) {
            int rl = wrow + gid + rh * 8;                 // local row 0..127
            int grow = s * R_RES + qb * 128 + rl;
            int cl = ct * 8 + 2 * tg;                     // local col 0..31
            float2 gt = *(const float2*)&g_gate[(size_t)grow * 256 + h * CH + cl];
            Qs[rl * 36 + cl]     = ftf32(accO[ct][rh * 2 + 0] * inv[rh] * gt.x);
            Qs[rl * 36 + cl + 1] = ftf32(accO[ct][rh * 2 + 1] * inv[rh] * gt.y);
        }
    }
    __syncthreads();

    // emit fragment-ordered, fully coalesced float4 stores
    const int f = tid * 4;
    const int kc = f >> 8, rem = f & 255;
    const int mt2 = rem >> 7, lp = (rem >> 2) & 31;
    const int gid2 = lp >> 2, tg2 = lp & 3;
    const int cb = kc * 8 + tg2;
#pragma unroll
    for (int it = 0; it < 4; it++) {
        int rbase = it * 32 + mt2 * 16 + gid2;
        float4 v;
        v.x = Qs[rbase * 36 + cb];
        v.y = Qs[(rbase + 8) * 36 + cb];
        v.z = Qs[rbase * 36 + cb + 4];
        v.w = Qs[(rbase + 8) * 36 + cb + 4];
        size_t rbg = (size_t)(s * 8 + qb * 4 + it);
        *(float4*)(g_of + rbg * 8192 + h * 1024 + f) = v;
    }
}

// ---------------- launch ----------------
extern "C" void kernel_launch(void* const* d_in, const int* in_sizes, int n_in,
                              void* d_out, int out_size) {
    (void)in_sizes; (void)n_in; (void)out_size;
    const float* m   = (const float*)d_in[0];
    const float* z   = (const float*)d_in[1];
    const float* lmw = (const float*)d_in[2];
    const float* lmb = (const float*)d_in[3];
    const float* lzw = (const float*)d_in[4];
    const float* lzb = (const float*)d_in[5];
    const float* Wz  = (const float*)d_in[6];
    const float* Wq  = (const float*)d_in[7];
    const float* Wk  = (const float*)d_in[8];
    const float* Wv  = (const float*)d_in[9];
    const float* Wg  = (const float*)d_in[10];
    const float* bg  = (const float*)d_in[11];
    const float* Wo  = (const float*)d_in[12];
    const float* bo  = (const float*)d_in[13];

    cudaFuncSetAttribute(tf32gemm_kernel, cudaFuncAttributeMaxDynamicSharedMemorySize, SM_BYTES);

    ln_m_kernel<<<2048, 256>>>(m, lmw, lmb);
    ln_z_bias_kernel<<<8192, 256>>>(z, lzw, lzb, Wz);
    repack_kernel<<<320, 256>>>(Wq, Wk, Wv, Wg, Wo);

    tf32gemm_kernel<<<dim3(16, 512), 256, SM_BYTES>>>(bg, nullptr, nullptr, 1);

    attn_mma_kernel<<<dim3(2, S_SEQ * NH), 256>>>();

    tf32gemm_kernel<<<dim3(4, 512), 256, SM_BYTES>>>(nullptr, bo, (float*)d_out, 0);
}

// round 8
// speedup vs baseline: 1.6316x; 1.0673x over previous
#include <cuda_runtime.h>
#include <math.h>
#include <stdint.h>

#define S_SEQ 256
#define R_RES 256
#define CM 256
#define CZ 128
#define NH 8
#define CH 32
#define HC 256
#define LNEPS 1e-5f

// ---------------- scratch (device globals; no allocation allowed) ----------------
// fragment layout for a 32-row x 8-col chunk (rb = row/32, kc = col/8):
//   offset = (rb*32 + kc)*256 + mt*128 + lane*4 + f
//   row = rb*32 + mt*16 + sub*8 + (lane>>2), col = kc*8 + half*4 + (lane&3), f = sub + 2*half
__device__ float g_mnf[(size_t)S_SEQ * R_RES * CM];      // 64 MB  LN(m), tf32, frag layout
__device__ float g_q[(size_t)S_SEQ * R_RES * HC];        // 64 MB  flat (s, r, h*32+c)
__device__ float g_k[(size_t)S_SEQ * R_RES * HC];        // 64 MB
__device__ float g_v[(size_t)S_SEQ * R_RES * HC];        // 64 MB
__device__ float g_gate[(size_t)S_SEQ * R_RES * HC];     // 64 MB  sigmoid(mn@Wg+bg)
__device__ float g_of[(size_t)S_SEQ * R_RES * HC];       // 64 MB  gate .* attn_out, tf32, frag layout
__device__ float g_bias[(size_t)NH * R_RES * R_RES];     //  2 MB  [h][q][k]
__device__ float4 g_wf4[5 * 16384];                      //  2.5 MB B frags [z][kt][nb][ks][ntp][lane]

__device__ __forceinline__ float ftf32(float x) {
    uint32_t u;
    asm("cvt.rna.tf32.f32 %0, %1;" : "=r"(u) : "f"(x));
    return __uint_as_float(u);
}
__device__ __forceinline__ uint32_t ftf32u(float x) {
    uint32_t u;
    asm("cvt.rna.tf32.f32 %0, %1;" : "=r"(u) : "f"(x));
    return u;
}
__device__ __forceinline__ uint32_t smem_u32(const void* p) {
    uint32_t a;
    asm("{ .reg .u64 t; cvta.to.shared.u64 t, %1; cvt.u32.u64 %0, t; }" : "=r"(a) : "l"(p));
    return a;
}
__device__ __forceinline__ void cp16(uint32_t dst, const void* src) {
    asm volatile("cp.async.cg.shared.global [%0], [%1], 16;" :: "r"(dst), "l"(src));
}

#define MMA4(d, a, b)                                                              \
    asm volatile("mma.sync.aligned.m16n8k8.row.col.f32.tf32.tf32.f32 "             \
                 "{%0,%1,%2,%3},{%4,%5,%6,%7},{%8,%9},{%0,%1,%2,%3};"              \
                 : "+f"(d[0]), "+f"(d[1]), "+f"(d[2]), "+f"(d[3])                  \
                 : "r"(a[0]), "r"(a[1]), "r"(a[2]), "r"(a[3]), "r"(b[0]), "r"(b[1]))

// ---------------- LayerNorm m -> fragment-ordered tf32 g_mnf ----------------
__global__ void __launch_bounds__(256) ln_m_kernel(const float* __restrict__ x,
                                                   const float* __restrict__ w,
                                                   const float* __restrict__ b) {
    __shared__ float sln[32 * 260];
    const int tid = threadIdx.x;
    const int wid = tid >> 5, lane = tid & 31;

    const float4 w0 = *(const float4*)(w + lane * 8);
    const float4 w1 = *(const float4*)(w + lane * 8 + 4);
    const float4 b0 = *(const float4*)(b + lane * 8);
    const float4 b1 = *(const float4*)(b + lane * 8 + 4);

#pragma unroll 1
    for (int q = 0; q < 4; q++) {
        int lr = wid * 4 + q;
        size_t row = (size_t)blockIdx.x * 32 + lr;
        const float* xp = x + row * CM + lane * 8;
        float4 v0 = *(const float4*)xp;
        float4 v1 = *(const float4*)(xp + 4);
        float s  = v0.x + v0.y + v0.z + v0.w + v1.x + v1.y + v1.z + v1.w;
        float sq = v0.x * v0.x + v0.y * v0.y + v0.z * v0.z + v0.w * v0.w
                 + v1.x * v1.x + v1.y * v1.y + v1.z * v1.z + v1.w * v1.w;
#pragma unroll
        for (int st = 16; st > 0; st >>= 1) {
            s  += __shfl_xor_sync(0xffffffff, s, st);
            sq += __shfl_xor_sync(0xffffffff, sq, st);
        }
        float mean = s * (1.0f / CM);
        float inv  = rsqrtf(sq * (1.0f / CM) - mean * mean + LNEPS);
        float* sp = &sln[lr * 260 + lane * 8];
        sp[0] = ftf32((v0.x - mean) * inv * w0.x + b0.x);
        sp[1] = ftf32((v0.y - mean) * inv * w0.y + b0.y);
        sp[2] = ftf32((v0.z - mean) * inv * w0.z + b0.z);
        sp[3] = ftf32((v0.w - mean) * inv * w0.w + b0.w);
        sp[4] = ftf32((v1.x - mean) * inv * w1.x + b1.x);
        sp[5] = ftf32((v1.y - mean) * inv * w1.y + b1.y);
        sp[6] = ftf32((v1.z - mean) * inv * w1.z + b1.z);
        sp[7] = ftf32((v1.w - mean) * inv * w1.w + b1.w);
    }
    __syncthreads();

    float* dst = g_mnf + (size_t)blockIdx.x * 8192;
#pragma unroll
    for (int it = 0; it < 8; it++) {
        int i = tid + it * 256;
        int f = i * 4;
        int kc = f >> 8, rem = f & 255;
        int mt = rem >> 7, lp = (rem >> 2) & 31;
        int gid2 = lp >> 2, tg2 = lp & 3;
        int cb = kc * 8 + tg2;
        float4 v;
        v.x = sln[(mt * 16 + 0 + gid2) * 260 + cb];
        v.y = sln[(mt * 16 + 8 + gid2) * 260 + cb];
        v.z = sln[(mt * 16 + 0 + gid2) * 260 + cb + 4];
        v.w = sln[(mt * 16 + 8 + gid2) * 260 + cb + 4];
        *(float4*)(dst + f) = v;
    }
}

// ---------------- LN(z) + pair-bias: one warp per (q,k) ----------------
__global__ void __launch_bounds__(256) ln_z_bias_kernel(
    const float* __restrict__ z, const float* __restrict__ w,
    const float* __restrict__ b, const float* __restrict__ Wz) {
    __shared__ float sWzT[8 * 128];
    const int tid = threadIdx.x;
    for (int i = tid; i < 1024; i += 256) {
        int zz = i >> 3, h = i & 7;
        sWzT[h * 128 + zz] = Wz[i];
    }
    __syncthreads();

    const int wid = tid >> 5, lane = tid & 31;
    const int qk = blockIdx.x * 8 + wid;
    const int q = qk >> 8, k = qk & 255;
    float4 v = *(const float4*)(z + (size_t)qk * CZ + 4 * lane);
    float s  = v.x + v.y + v.z + v.w;
    float sq = v.x * v.x + v.y * v.y + v.z * v.z + v.w * v.w;
#pragma unroll
    for (int st = 16; st > 0; st >>= 1) {
        s  += __shfl_xor_sync(0xffffffff, s, st);
        sq += __shfl_xor_sync(0xffffffff, sq, st);
    }
    float mean = s * (1.0f / CZ);
    float inv  = rsqrtf(sq * (1.0f / CZ) - mean * mean + LNEPS);
    float4 w4 = *(const float4*)(w + 4 * lane);
    float4 b4 = *(const float4*)(b + 4 * lane);
    float4 zn;
    zn.x = (v.x - mean) * inv * w4.x + b4.x;
    zn.y = (v.y - mean) * inv * w4.y + b4.y;
    zn.z = (v.z - mean) * inv * w4.z + b4.z;
    zn.w = (v.w - mean) * inv * w4.w + b4.w;

    float p[8];
#pragma unroll
    for (int h = 0; h < 8; h++) {
        float4 wz = *(const float4*)&sWzT[h * 128 + 4 * lane];
        p[h] = zn.x * wz.x + zn.y * wz.y + zn.z * wz.z + zn.w * wz.w;
    }
#pragma unroll
    for (int st = 16; st > 0; st >>= 1) {
#pragma unroll
        for (int h = 0; h < 8; h++) p[h] += __shfl_xor_sync(0xffffffff, p[h], st);
    }
    float outv = p[0];
#pragma unroll
    for (int h = 1; h < 8; h++) if (lane == h) outv = p[h];
    if (lane < 8)
        g_bias[((size_t)lane * R_RES + q) * R_RES + k] = outv;
}

// ---------------- B-fragment repack: [zz][kt][nb][ks][ntp][lane] float4 ----------------
__global__ void __launch_bounds__(256) repack_kernel(
    const float* __restrict__ w0, const float* __restrict__ w1,
    const float* __restrict__ w2, const float* __restrict__ w3,
    const float* __restrict__ w4) {
    int t = blockIdx.x * 256 + threadIdx.x;       // < 81920
    int lane = t & 31;
    int ntp = (t >> 5) & 1;
    int ks = (t >> 6) & 3;
    int nb = (t >> 8) & 7;
    int kt = (t >> 11) & 7;
    int zz = t >> 14;
    const float* W = (zz == 0) ? w0 : (zz == 1) ? w1 : (zz == 2) ? w2 : (zz == 3) ? w3 : w4;
    int krow = kt * 32 + ks * 8 + (lane & 3);
    int gid = lane >> 2;
    int ncolA = nb * 32 + (2 * ntp) * 8 + gid;
    int ncolB = ncolA + 8;
    float4 v;
    v.x = ftf32(W[krow * 256 + ncolA]);
    v.y = ftf32(W[(krow + 4) * 256 + ncolA]);
    v.z = ftf32(W[krow * 256 + ncolB]);
    v.w = ftf32(W[(krow + 4) * 256 + ncolB]);
    g_wf4[t] = v;
}

// ---------------- cp.async-pipelined tf32 GEMM: C(65536x256) = A @ W ----------------
// CTA tile 128x128, warp tile 32x64 (8 warps = 4m x 2n), BK=32, 3-stage pipeline.
// fused==1: blockIdx.x = nbp2*4+z; z=0/1/2 -> q/k/v (flat), z=3 -> gate (sigmoid+bg)
// fused==0: A = g_of (frag layout), out = d_out + bo
#define ASTAGE_F 4096
#define STAGE_F  8192
#define SM_BYTES (3 * STAGE_F * 4)   // 98304

__device__ __forceinline__ void stage_tile(uint32_t smb, int buf, int kt, int by, int nbp2,
                                           int tid, const float* Af, const float4* Bw) {
    uint32_t db = smb + (uint32_t)buf * (STAGE_F * 4);
#pragma unroll
    for (int it = 0; it < 4; it++) {
        int ca = tid + it * 256;
        int rb = ca >> 8, kc = (ca >> 6) & 3, c = ca & 63;
        const float* s = Af + ((size_t)(by * 128 + rb * 32 + kt * 4 + kc)) * 256 + c * 4;
        cp16(db + (uint32_t)(((rb * 4 + kc) * 256 + c * 4) * 4), s);
    }
#pragma unroll
    for (int it = 0; it < 4; it++) {
        int cb = tid + it * 256;                       // 1024 float4 per tile (128 cols)
        int nl = cb >> 8, inner = cb & 255;
        const float4* s = Bw + ((size_t)(kt * 8 + nbp2 * 4 + nl)) * 256 + inner;
        cp16(db + (uint32_t)((ASTAGE_F + nl * 1024 + inner * 4) * 4), s);
    }
}

__global__ void __launch_bounds__(256, 2) tf32gemm_kernel(
    const float* __restrict__ bias_g, const float* __restrict__ bias_o,
    float* __restrict__ out_ext, int fused) {

    extern __shared__ float sm[];
    const uint32_t smb = smem_u32(sm);
    const int tid = threadIdx.x;
    const int lane = tid & 31, wid = tid >> 5;
    const int gid = lane >> 2, tg = lane & 3;
    const int rbw = wid & 3;       // warp m-block (32 rows)
    const int nblw = wid >> 2;     // warp n-block (64 cols)
    const int nbp2 = fused ? (blockIdx.x >> 2) : blockIdx.x;   // 128-col half
    const int zz  = fused ? (blockIdx.x & 3) : 4;
    const int by  = blockIdx.y;

    const float* Af = fused ? g_mnf : g_of;
    const float4* Bw = g_wf4 + (size_t)zz * 16384;

    float acc[2][8][4];
#pragma unroll
    for (int mt = 0; mt < 2; mt++)
#pragma unroll
        for (int nt = 0; nt < 8; nt++)
#pragma unroll
            for (int j = 0; j < 4; j++) acc[mt][nt][j] = 0.f;

    stage_tile(smb, 0, 0, by, nbp2, tid, Af, Bw);
    asm volatile("cp.async.commit_group;" ::: "memory");
    stage_tile(smb, 1, 1, by, nbp2, tid, Af, Bw);
    asm volatile("cp.async.commit_group;" ::: "memory");

    int cur = 0, nxt = 2;
#pragma unroll 1
    for (int kt = 0; kt < 8; kt++) {
        asm volatile("cp.async.wait_group 1;" ::: "memory");
        __syncthreads();
        if (kt < 6) stage_tile(smb, nxt, kt + 2, by, nbp2, tid, Af, Bw);
        asm volatile("cp.async.commit_group;" ::: "memory");

        const float* As = sm + cur * STAGE_F;
        const float* Bs = As + ASTAGE_F;
#pragma unroll
        for (int kc = 0; kc < 4; kc++) {
            float4 va0 = *(const float4*)&As[(rbw * 4 + kc) * 256 + lane * 4];
            float4 va1 = *(const float4*)&As[(rbw * 4 + kc) * 256 + 128 + lane * 4];
            uint32_t a0[4] = {__float_as_uint(va0.x), __float_as_uint(va0.y),
                              __float_as_uint(va0.z), __float_as_uint(va0.w)};
            uint32_t a1[4] = {__float_as_uint(va1.x), __float_as_uint(va1.y),
                              __float_as_uint(va1.z), __float_as_uint(va1.w)};
#pragma unroll
            for (int nbl2 = 0; nbl2 < 2; nbl2++) {
                const int nbloc = nblw * 2 + nbl2;
#pragma unroll
                for (int ntp = 0; ntp < 2; ntp++) {
                    float4 vb = *(const float4*)&Bs[nbloc * 1024 + ((kc * 2 + ntp) * 32 + lane) * 4];
                    uint32_t b0[2] = {__float_as_uint(vb.x), __float_as_uint(vb.y)};
                    uint32_t b1[2] = {__float_as_uint(vb.z), __float_as_uint(vb.w)};
                    const int nt = nbl2 * 4 + 2 * ntp;
                    MMA4(acc[0][nt], a0, b0);
                    MMA4(acc[1][nt], a1, b0);
                    MMA4(acc[0][nt + 1], a0, b1);
                    MMA4(acc[1][nt + 1], a1, b1);
                }
            }
        }
        cur = (cur == 2) ? 0 : cur + 1;
        nxt = (nxt == 2) ? 0 : nxt + 1;
    }

    // ---- epilogue (flat, coalesced float2) ----
    float* out = (!fused) ? out_ext
               : (zz == 0) ? g_q : (zz == 1) ? g_k : (zz == 2) ? g_v : g_gate;
#pragma unroll
    for (int mt = 0; mt < 2; mt++) {
#pragma unroll
        for (int nt = 0; nt < 8; nt++) {
#pragma unroll
            for (int half = 0; half < 2; half++) {
                int gr = by * 128 + rbw * 32 + mt * 16 + gid + half * 8;
                int gc = nbp2 * 128 + (nblw * 2 + (nt >> 2)) * 32 + (nt & 3) * 8 + tg * 2;
                float2 val;
                val.x = acc[mt][nt][half * 2 + 0];
                val.y = acc[mt][nt][half * 2 + 1];
                if (fused && zz == 3) {
                    val.x = 1.f / (1.f + __expf(-(val.x + bias_g[gc + 0])));
                    val.y = 1.f / (1.f + __expf(-(val.y + bias_g[gc + 1])));
                } else if (!fused) {
                    val.x += bias_o[gc + 0];
                    val.y += bias_o[gc + 1];
                }
                *(float2*)(out + (size_t)gr * 256 + gc) = val;
            }
        }
    }
}

// ---------------- tensor-core flash attention; gated, frag-ordered coalesced output ------
__global__ void __launch_bounds__(256, 2) attn_mma_kernel() {
    const int sh = blockIdx.y;
    const int s = sh >> 3, h = sh & 7;
    const int qb = blockIdx.x;
    const int tid = threadIdx.x;
    const int lane = tid & 31, wid = tid >> 5;
    const int gid = lane >> 2, tg = lane & 3;
    const int wrow = wid * 16;

    __shared__ __align__(16) float Qs[128 * 36];   // reused for output staging
    __shared__ __align__(16) float Ks[64 * 36];
    __shared__ __align__(16) float Vs[64 * 40];

    const float* qg = g_q + ((size_t)(s * R_RES + qb * 128)) * HC + h * CH;
#pragma unroll
    for (int it = 0; it < 4; it++) {
        int i = tid + it * 256;
        int r = i >> 3, c4 = i & 7;
        float4 v = *(const float4*)(qg + (size_t)r * HC + c4 * 4);
        v.x = ftf32(v.x); v.y = ftf32(v.y); v.z = ftf32(v.z); v.w = ftf32(v.w);
        *(float4*)&Qs[r * 36 + c4 * 4] = v;
    }
    __syncthreads();

    uint32_t qa[4][4];
#pragma unroll
    for (int ks = 0; ks < 4; ks++) {
        int r0 = wrow + gid;
        qa[ks][0] = __float_as_uint(Qs[r0 * 36 + ks * 8 + tg]);
        qa[ks][1] = __float_as_uint(Qs[(r0 + 8) * 36 + ks * 8 + tg]);
        qa[ks][2] = __float_as_uint(Qs[r0 * 36 + ks * 8 + tg + 4]);
        qa[ks][3] = __float_as_uint(Qs[(r0 + 8) * 36 + ks * 8 + tg + 4]);
    }

    float m_i[2] = {-3.0e38f, -3.0e38f};
    float l_i[2] = {0.f, 0.f};
    float accO[4][4];
#pragma unroll
    for (int ct = 0; ct < 4; ct++)
#pragma unroll
        for (int j = 0; j < 4; j++) accO[ct][j] = 0.f;

    const float scale = 0.17677669529663687f;
    const float* bias_r0 = g_bias + ((size_t)h * R_RES + qb * 128 + wrow + gid) * R_RES;
    const float* bias_r1 = bias_r0 + 8 * R_RES;

    for (int kt = 0; kt < 4; kt++) {
        const float* kg = g_k + ((size_t)(s * R_RES + kt * 64)) * HC + h * CH;
        const float* vg = g_v + ((size_t)(s * R_RES + kt * 64)) * HC + h * CH;
#pragma unroll
        for (int it = 0; it < 2; it++) {
            int i = tid + it * 256;
            int r = i >> 3, c4 = i & 7;
            float4 kv = *(const float4*)(kg + (size_t)r * HC + c4 * 4);
            kv.x = ftf32(kv.x); kv.y = ftf32(kv.y); kv.z = ftf32(kv.z); kv.w = ftf32(kv.w);
            *(float4*)&Ks[r * 36 + c4 * 4] = kv;
            float4 vv = *(const float4*)(vg + (size_t)r * HC + c4 * 4);
            vv.x = ftf32(vv.x); vv.y = ftf32(vv.y); vv.z = ftf32(vv.z); vv.w = ftf32(vv.w);
            *(float4*)&Vs[r * 40 + c4 * 4] = vv;
        }
        __syncthreads();

        float acc[8][4];
#pragma unroll
        for (int nt = 0; nt < 8; nt++)
#pragma unroll
            for (int j = 0; j < 4; j++) acc[nt][j] = 0.f;

#pragma unroll
        for (int nt = 0; nt < 8; nt++) {
            const float* kr = &Ks[(nt * 8 + gid) * 36 + tg];
            uint32_t b[2];
#pragma unroll
            for (int ks = 0; ks < 4; ks++) {
                b[0] = __float_as_uint(kr[ks * 8]);
                b[1] = __float_as_uint(kr[ks * 8 + 4]);
                MMA4(acc[nt], qa[ks], b);
            }
        }

        float2 bb0[8], bb1[8];
#pragma unroll
        for (int nt = 0; nt < 8; nt++) {
            int col = kt * 64 + nt * 8 + 2 * tg;
            bb0[nt] = *(const float2*)&bias_r0[col];
            bb1[nt] = *(const float2*)&bias_r1[col];
        }
#pragma unroll
        for (int nt = 0; nt < 8; nt++) {
            acc[nt][0] = fmaf(acc[nt][0], scale, bb0[nt].x);
            acc[nt][1] = fmaf(acc[nt][1], scale, bb0[nt].y);
            acc[nt][2] = fmaf(acc[nt][2], scale, bb1[nt].x);
            acc[nt][3] = fmaf(acc[nt][3], scale, bb1[nt].y);
        }

        float mt[2] = {-3.0e38f, -3.0e38f};
#pragma unroll
        for (int nt = 0; nt < 8; nt++) {
            mt[0] = fmaxf(mt[0], fmaxf(acc[nt][0], acc[nt][1]));
            mt[1] = fmaxf(mt[1], fmaxf(acc[nt][2], acc[nt][3]));
        }
#pragma unroll
        for (int rh = 0; rh < 2; rh++) {
            mt[rh] = fmaxf(mt[rh], __shfl_xor_sync(0xffffffff, mt[rh], 1));
            mt[rh] = fmaxf(mt[rh], __shfl_xor_sync(0xffffffff, mt[rh], 2));
            float mnew = fmaxf(m_i[rh], mt[rh]);
            float corr = __expf(m_i[rh] - mnew);
            m_i[rh] = mnew;
            l_i[rh] *= corr;
#pragma unroll
            for (int ct = 0; ct < 4; ct++) {
                accO[ct][rh * 2 + 0] *= corr;
                accO[ct][rh * 2 + 1] *= corr;
            }
        }
#pragma unroll
        for (int nt = 0; nt < 8; nt++) {
            acc[nt][0] = __expf(acc[nt][0] - m_i[0]);
            acc[nt][1] = __expf(acc[nt][1] - m_i[0]);
            acc[nt][2] = __expf(acc[nt][2] - m_i[1]);
            acc[nt][3] = __expf(acc[nt][3] - m_i[1]);
            l_i[0] += acc[nt][0] + acc[nt][1];
            l_i[1] += acc[nt][2] + acc[nt][3];
        }

        const int src = 4 * gid + (tg >> 1);
        const bool odd = tg & 1;
#pragma unroll
        for (int nt = 0; nt < 8; nt++) {
            float v0  = __shfl_sync(0xffffffff, acc[nt][0], src);
            float v1  = __shfl_sync(0xffffffff, acc[nt][1], src);
            float w0  = __shfl_sync(0xffffffff, acc[nt][2], src);
            float w1  = __shfl_sync(0xffffffff, acc[nt][3], src);
            float v0b = __shfl_sync(0xffffffff, acc[nt][0], src + 2);
            float v1b = __shfl_sync(0xffffffff, acc[nt][1], src + 2);
            float w0b = __shfl_sync(0xffffffff, acc[nt][2], src + 2);
            float w1b = __shfl_sync(0xffffffff, acc[nt][3], src + 2);
            uint32_t pa[4];
            pa[0] = ftf32u(odd ? v1 : v0);
            pa[1] = ftf32u(odd ? w1 : w0);
            pa[2] = ftf32u(odd ? v1b : v0b);
            pa[3] = ftf32u(odd ? w1b : w0b);
            const float* vr = &Vs[(nt * 8 + tg) * 40 + gid];
            uint32_t b[2];
#pragma unroll
            for (int ct = 0; ct < 4; ct++) {
                b[0] = __float_as_uint(vr[ct * 8]);
                b[1] = __float_as_uint(vr[ct * 8 + 160]);
                MMA4(accO[ct], pa, b);
            }
        }
        __syncthreads();
    }

    float inv[2];
#pragma unroll
    for (int rh = 0; rh < 2; rh++) {
        float l = l_i[rh];
        l += __shfl_xor_sync(0xffffffff, l, 1);
        l += __shfl_xor_sync(0xffffffff, l, 2);
        inv[rh] = 1.0f / l;
    }

    // stage gated output into smem (local layout 128 x 32, stride 36)
#pragma unroll
    for (int ct = 0; ct < 4; ct++) {
#pragma unroll
        for (int rh = 0; rh < 2; rh++) {
            int rl = wrow + gid + rh * 8;
            int grow = s * R_RES + qb * 128 + rl;
            int cl = ct * 8 + 2 * tg;
            float2 gt = *(const float2*)&g_gate[(size_t)grow * 256 + h * CH + cl];
            Qs[rl * 36 + cl]     = ftf32(accO[ct][rh * 2 + 0] * inv[rh] * gt.x);
            Qs[rl * 36 + cl + 1] = ftf32(accO[ct][rh * 2 + 1] * inv[rh] * gt.y);
        }
    }
    __syncthreads();

    // emit fragment-ordered, fully coalesced float4 stores
    const int f = tid * 4;
    const int kc = f >> 8, rem = f & 255;
    const int mt2 = rem >> 7, lp = (rem >> 2) & 31;
    const int gid2 = lp >> 2, tg2 = lp & 3;
    const int cb = kc * 8 + tg2;
#pragma unroll
    for (int it = 0; it < 4; it++) {
        int rbase = it * 32 + mt2 * 16 + gid2;
        float4 v;
        v.x = Qs[rbase * 36 + cb];
        v.y = Qs[(rbase + 8) * 36 + cb];
        v.z = Qs[rbase * 36 + cb + 4];
        v.w = Qs[(rbase + 8) * 36 + cb + 4];
        size_t rbg = (size_t)(s * 8 + qb * 4 + it);
        *(float4*)(g_of + rbg * 8192 + h * 1024 + f) = v;
    }
}

// ---------------- launch ----------------
extern "C" void kernel_launch(void* const* d_in, const int* in_sizes, int n_in,
                              void* d_out, int out_size) {
    (void)in_sizes; (void)n_in; (void)out_size;
    const float* m   = (const float*)d_in[0];
    const float* z   = (const float*)d_in[1];
    const float* lmw = (const float*)d_in[2];
    const float* lmb = (const float*)d_in[3];
    const float* lzw = (const float*)d_in[4];
    const float* lzb = (const float*)d_in[5];
    const float* Wz  = (const float*)d_in[6];
    const float* Wq  = (const float*)d_in[7];
    const float* Wk  = (const float*)d_in[8];
    const float* Wv  = (const float*)d_in[9];
    const float* Wg  = (const float*)d_in[10];
    const float* bg  = (const float*)d_in[11];
    const float* Wo  = (const float*)d_in[12];
    const float* bo  = (const float*)d_in[13];

    cudaFuncSetAttribute(tf32gemm_kernel, cudaFuncAttributeMaxDynamicSharedMemorySize, SM_BYTES);

    ln_m_kernel<<<2048, 256>>>(m, lmw, lmb);
    ln_z_bias_kernel<<<8192, 256>>>(z, lzw, lzb, Wz);
    repack_kernel<<<320, 256>>>(Wq, Wk, Wv, Wg, Wo);

    tf32gemm_kernel<<<dim3(8, 512), 256, SM_BYTES>>>(bg, nullptr, nullptr, 1);

    attn_mma_kernel<<<dim3(2, S_SEQ * NH), 256>>>();

    tf32gemm_kernel<<<dim3(2, 512), 256, SM_BYTES>>>(nullptr, bo, (float*)d_out, 0);
}

// round 9
// speedup vs baseline: 1.6881x; 1.0346x over previous
#include <cuda_runtime.h>
#include <math.h>
#include <stdint.h>

#define S_SEQ 256
#define R_RES 256
#define CM 256
#define CZ 128
#define NH 8
#define CH 32
#define HC 256
#define LNEPS 1e-5f
#define LOG2E 1.4426950408889634f

// ---------------- scratch (device globals; no allocation allowed) ----------------
__device__ float g_mnf[(size_t)S_SEQ * R_RES * CM];      // 64 MB  LN(m), tf32, frag layout
__device__ float g_q[(size_t)S_SEQ * R_RES * HC];        // 64 MB  flat (s, r, h*32+c), tf32
__device__ float g_k[(size_t)S_SEQ * R_RES * HC];        // 64 MB  tf32
__device__ float g_v[(size_t)S_SEQ * R_RES * HC];        // 64 MB  tf32
__device__ float g_gate[(size_t)S_SEQ * R_RES * HC];     // 64 MB  sigmoid(mn@Wg+bg)
__device__ float g_of[(size_t)S_SEQ * R_RES * HC];       // 64 MB  gate .* attn_out, tf32, frag layout
__device__ float g_bias[(size_t)NH * R_RES * R_RES];     //  2 MB  [h][q][k], pre-scaled by log2e
__device__ float4 g_wf4[5 * 16384];                      //  2.5 MB B frags

__device__ __forceinline__ float ftf32(float x) {
    uint32_t u;
    asm("cvt.rna.tf32.f32 %0, %1;" : "=r"(u) : "f"(x));
    return __uint_as_float(u);
}
__device__ __forceinline__ uint32_t ftf32u(float x) {
    uint32_t u;
    asm("cvt.rna.tf32.f32 %0, %1;" : "=r"(u) : "f"(x));
    return u;
}
__device__ __forceinline__ float fexp2(float x) {
    float r;
    asm("ex2.approx.f32 %0, %1;" : "=f"(r) : "f"(x));
    return r;
}
__device__ __forceinline__ uint32_t smem_u32(const void* p) {
    uint32_t a;
    asm("{ .reg .u64 t; cvta.to.shared.u64 t, %1; cvt.u32.u64 %0, t; }" : "=r"(a) : "l"(p));
    return a;
}
__device__ __forceinline__ void cp16(uint32_t dst, const void* src) {
    asm volatile("cp.async.cg.shared.global [%0], [%1], 16;" :: "r"(dst), "l"(src));
}

#define MMA4(d, a, b)                                                              \
    asm volatile("mma.sync.aligned.m16n8k8.row.col.f32.tf32.tf32.f32 "             \
                 "{%0,%1,%2,%3},{%4,%5,%6,%7},{%8,%9},{%0,%1,%2,%3};"              \
                 : "+f"(d[0]), "+f"(d[1]), "+f"(d[2]), "+f"(d[3])                  \
                 : "r"(a[0]), "r"(a[1]), "r"(a[2]), "r"(a[3]), "r"(b[0]), "r"(b[1]))

// ================= prep mega-kernel: ln_m (0..2047) | ln_z+bias (2048..10239) | repack =====
__global__ void __launch_bounds__(256) prep_kernel(
    const float* __restrict__ x, const float* __restrict__ lmw, const float* __restrict__ lmb,
    const float* __restrict__ z, const float* __restrict__ lzw, const float* __restrict__ lzb,
    const float* __restrict__ Wz,
    const float* __restrict__ w0, const float* __restrict__ w1, const float* __restrict__ w2,
    const float* __restrict__ w3, const float* __restrict__ w4) {

    __shared__ float sh[32 * 260];
    const int tid = threadIdx.x;
    const int wid = tid >> 5, lane = tid & 31;
    const int bx = blockIdx.x;

    if (bx < 2048) {
        // ---- LayerNorm m -> fragment-ordered tf32 g_mnf ----
        const float4 w0v = *(const float4*)(lmw + lane * 8);
        const float4 w1v = *(const float4*)(lmw + lane * 8 + 4);
        const float4 b0v = *(const float4*)(lmb + lane * 8);
        const float4 b1v = *(const float4*)(lmb + lane * 8 + 4);
#pragma unroll 1
        for (int q = 0; q < 4; q++) {
            int lr = wid * 4 + q;
            size_t row = (size_t)bx * 32 + lr;
            const float* xp = x + row * CM + lane * 8;
            float4 v0 = *(const float4*)xp;
            float4 v1 = *(const float4*)(xp + 4);
            float s  = v0.x + v0.y + v0.z + v0.w + v1.x + v1.y + v1.z + v1.w;
            float sq = v0.x * v0.x + v0.y * v0.y + v0.z * v0.z + v0.w * v0.w
                     + v1.x * v1.x + v1.y * v1.y + v1.z * v1.z + v1.w * v1.w;
#pragma unroll
            for (int st = 16; st > 0; st >>= 1) {
                s  += __shfl_xor_sync(0xffffffff, s, st);
                sq += __shfl_xor_sync(0xffffffff, sq, st);
            }
            float mean = s * (1.0f / CM);
            float inv  = rsqrtf(sq * (1.0f / CM) - mean * mean + LNEPS);
            float* sp = &sh[lr * 260 + lane * 8];
            sp[0] = ftf32((v0.x - mean) * inv * w0v.x + b0v.x);
            sp[1] = ftf32((v0.y - mean) * inv * w0v.y + b0v.y);
            sp[2] = ftf32((v0.z - mean) * inv * w0v.z + b0v.z);
            sp[3] = ftf32((v0.w - mean) * inv * w0v.w + b0v.w);
            sp[4] = ftf32((v1.x - mean) * inv * w1v.x + b1v.x);
            sp[5] = ftf32((v1.y - mean) * inv * w1v.y + b1v.y);
            sp[6] = ftf32((v1.z - mean) * inv * w1v.z + b1v.z);
            sp[7] = ftf32((v1.w - mean) * inv * w1v.w + b1v.w);
        }
        __syncthreads();

        float* dst = g_mnf + (size_t)bx * 8192;
#pragma unroll
        for (int it = 0; it < 8; it++) {
            int i = tid + it * 256;
            int f = i * 4;
            int kc = f >> 8, rem = f & 255;
            int mt = rem >> 7, lp = (rem >> 2) & 31;
            int gid2 = lp >> 2, tg2 = lp & 3;
            int cb = kc * 8 + tg2;
            float4 v;
            v.x = sh[(mt * 16 + 0 + gid2) * 260 + cb];
            v.y = sh[(mt * 16 + 8 + gid2) * 260 + cb];
            v.z = sh[(mt * 16 + 0 + gid2) * 260 + cb + 4];
            v.w = sh[(mt * 16 + 8 + gid2) * 260 + cb + 4];
            *(float4*)(dst + f) = v;
        }
    } else if (bx < 10240) {
        // ---- LN(z) + pair-bias (pre-scaled by log2e): one warp per (q,k) ----
        for (int i = tid; i < 1024; i += 256) {
            int zz = i >> 3, h = i & 7;
            sh[h * 128 + zz] = Wz[i];
        }
        __syncthreads();

        const int qk = (bx - 2048) * 8 + wid;
        const int q = qk >> 8, k = qk & 255;
        float4 v = *(const float4*)(z + (size_t)qk * CZ + 4 * lane);
        float s  = v.x + v.y + v.z + v.w;
        float sq = v.x * v.x + v.y * v.y + v.z * v.z + v.w * v.w;
#pragma unroll
        for (int st = 16; st > 0; st >>= 1) {
            s  += __shfl_xor_sync(0xffffffff, s, st);
            sq += __shfl_xor_sync(0xffffffff, sq, st);
        }
        float mean = s * (1.0f / CZ);
        float inv  = rsqrtf(sq * (1.0f / CZ) - mean * mean + LNEPS);
        float4 w4 = *(const float4*)(lzw + 4 * lane);
        float4 b4 = *(const float4*)(lzb + 4 * lane);
        float4 zn;
        zn.x = (v.x - mean) * inv * w4.x + b4.x;
        zn.y = (v.y - mean) * inv * w4.y + b4.y;
        zn.z = (v.z - mean) * inv * w4.z + b4.z;
        zn.w = (v.w - mean) * inv * w4.w + b4.w;

        float p[8];
#pragma unroll
        for (int h = 0; h < 8; h++) {
            float4 wz = *(const float4*)&sh[h * 128 + 4 * lane];
            p[h] = zn.x * wz.x + zn.y * wz.y + zn.z * wz.z + zn.w * wz.w;
        }
#pragma unroll
        for (int st = 16; st > 0; st >>= 1) {
#pragma unroll
            for (int h = 0; h < 8; h++) p[h] += __shfl_xor_sync(0xffffffff, p[h], st);
        }
        float outv = p[0];
#pragma unroll
        for (int h = 1; h < 8; h++) if (lane == h) outv = p[h];
        if (lane < 8)
            g_bias[((size_t)lane * R_RES + q) * R_RES + k] = outv * LOG2E;
    } else {
        // ---- B-fragment repack ----
        int t = (bx - 10240) * 256 + tid;       // < 81920
        int ln2 = t & 31;
        int ntp = (t >> 5) & 1;
        int ks = (t >> 6) & 3;
        int nb = (t >> 8) & 7;
        int kt = (t >> 11) & 7;
        int zz = t >> 14;
        const float* W = (zz == 0) ? w0 : (zz == 1) ? w1 : (zz == 2) ? w2 : (zz == 3) ? w3 : w4;
        int krow = kt * 32 + ks * 8 + (ln2 & 3);
        int gidr = ln2 >> 2;
        int ncolA = nb * 32 + (2 * ntp) * 8 + gidr;
        int ncolB = ncolA + 8;
        float4 v;
        v.x = ftf32(W[krow * 256 + ncolA]);
        v.y = ftf32(W[(krow + 4) * 256 + ncolA]);
        v.z = ftf32(W[krow * 256 + ncolB]);
        v.w = ftf32(W[(krow + 4) * 256 + ncolB]);
        g_wf4[t] = v;
    }
}

// ---------------- cp.async-pipelined tf32 GEMM: C(65536x256) = A @ W ----------------
#define ASTAGE_F 4096
#define STAGE_F  8192
#define SM_BYTES (3 * STAGE_F * 4)   // 98304

__device__ __forceinline__ void stage_tile(uint32_t smb, int buf, int kt, int by, int nbp2,
                                           int tid, const float* Af, const float4* Bw) {
    uint32_t db = smb + (uint32_t)buf * (STAGE_F * 4);
#pragma unroll
    for (int it = 0; it < 4; it++) {
        int ca = tid + it * 256;
        int rb = ca >> 8, kc = (ca >> 6) & 3, c = ca & 63;
        const float* s = Af + ((size_t)(by * 128 + rb * 32 + kt * 4 + kc)) * 256 + c * 4;
        cp16(db + (uint32_t)(((rb * 4 + kc) * 256 + c * 4) * 4), s);
    }
#pragma unroll
    for (int it = 0; it < 4; it++) {
        int cb = tid + it * 256;
        int nl = cb >> 8, inner = cb & 255;
        const float4* s = Bw + ((size_t)(kt * 8 + nbp2 * 4 + nl)) * 256 + inner;
        cp16(db + (uint32_t)((ASTAGE_F + nl * 1024 + inner * 4) * 4), s);
    }
}

__global__ void __launch_bounds__(256, 2) tf32gemm_kernel(
    const float* __restrict__ bias_g, const float* __restrict__ bias_o,
    float* __restrict__ out_ext, int fused) {

    extern __shared__ float sm[];
    const uint32_t smb = smem_u32(sm);
    const int tid = threadIdx.x;
    const int lane = tid & 31, wid = tid >> 5;
    const int gid = lane >> 2, tg = lane & 3;
    const int rbw = wid & 3;
    const int nblw = wid >> 2;
    const int nbp2 = fused ? (blockIdx.x >> 2) : blockIdx.x;
    const int zz  = fused ? (blockIdx.x & 3) : 4;
    const int by  = blockIdx.y;

    const float* Af = fused ? g_mnf : g_of;
    const float4* Bw = g_wf4 + (size_t)zz * 16384;

    float acc[2][8][4];
#pragma unroll
    for (int mt = 0; mt < 2; mt++)
#pragma unroll
        for (int nt = 0; nt < 8; nt++)
#pragma unroll
            for (int j = 0; j < 4; j++) acc[mt][nt][j] = 0.f;

    stage_tile(smb, 0, 0, by, nbp2, tid, Af, Bw);
    asm volatile("cp.async.commit_group;" ::: "memory");
    stage_tile(smb, 1, 1, by, nbp2, tid, Af, Bw);
    asm volatile("cp.async.commit_group;" ::: "memory");

    int cur = 0, nxt = 2;
#pragma unroll 1
    for (int kt = 0; kt < 8; kt++) {
        asm volatile("cp.async.wait_group 1;" ::: "memory");
        __syncthreads();
        if (kt < 6) stage_tile(smb, nxt, kt + 2, by, nbp2, tid, Af, Bw);
        asm volatile("cp.async.commit_group;" ::: "memory");

        const float* As = sm + cur * STAGE_F;
        const float* Bs = As + ASTAGE_F;
#pragma unroll
        for (int kc = 0; kc < 4; kc++) {
            float4 va0 = *(const float4*)&As[(rbw * 4 + kc) * 256 + lane * 4];
            float4 va1 = *(const float4*)&As[(rbw * 4 + kc) * 256 + 128 + lane * 4];
            uint32_t a0[4] = {__float_as_uint(va0.x), __float_as_uint(va0.y),
                              __float_as_uint(va0.z), __float_as_uint(va0.w)};
            uint32_t a1[4] = {__float_as_uint(va1.x), __float_as_uint(va1.y),
                              __float_as_uint(va1.z), __float_as_uint(va1.w)};
#pragma unroll
            for (int nbl2 = 0; nbl2 < 2; nbl2++) {
                const int nbloc = nblw * 2 + nbl2;
#pragma unroll
                for (int ntp = 0; ntp < 2; ntp++) {
                    float4 vb = *(const float4*)&Bs[nbloc * 1024 + ((kc * 2 + ntp) * 32 + lane) * 4];
                    uint32_t b0[2] = {__float_as_uint(vb.x), __float_as_uint(vb.y)};
                    uint32_t b1[2] = {__float_as_uint(vb.z), __float_as_uint(vb.w)};
                    const int nt = nbl2 * 4 + 2 * ntp;
                    MMA4(acc[0][nt], a0, b0);
                    MMA4(acc[1][nt], a1, b0);
                    MMA4(acc[0][nt + 1], a0, b1);
                    MMA4(acc[1][nt + 1], a1, b1);
                }
            }
        }
        cur = (cur == 2) ? 0 : cur + 1;
        nxt = (nxt == 2) ? 0 : nxt + 1;
    }

    // ---- epilogue ----
    float* out = (!fused) ? out_ext
               : (zz == 0) ? g_q : (zz == 1) ? g_k : (zz == 2) ? g_v : g_gate;
#pragma unroll
    for (int mt = 0; mt < 2; mt++) {
#pragma unroll
        for (int nt = 0; nt < 8; nt++) {
#pragma unroll
            for (int half = 0; half < 2; half++) {
                int gr = by * 128 + rbw * 32 + mt * 16 + gid + half * 8;
                int gc = nbp2 * 128 + (nblw * 2 + (nt >> 2)) * 32 + (nt & 3) * 8 + tg * 2;
                float2 val;
                val.x = acc[mt][nt][half * 2 + 0];
                val.y = acc[mt][nt][half * 2 + 1];
                if (fused && zz == 3) {
                    val.x = 1.f / (1.f + __expf(-(val.x + bias_g[gc + 0])));
                    val.y = 1.f / (1.f + __expf(-(val.y + bias_g[gc + 1])));
                } else if (!fused) {
                    val.x += bias_o[gc + 0];
                    val.y += bias_o[gc + 1];
                } else {
                    val.x = ftf32(val.x);     // pre-round q/k/v for attention
                    val.y = ftf32(val.y);
                }
                *(float2*)(out + (size_t)gr * 256 + gc) = val;
            }
        }
    }
}

// ---------------- tensor-core flash attention: cp.async K/V pipeline, exp2 softmax --------
// dynamic smem: Qs[128*36]=4608 | Ks[2][64*36]=4608 | Vs[2][64*40]=5120  (14336 floats)
#define ATT_QS 0
#define ATT_KS 4608
#define ATT_VS 9216
#define ATT_SMF 14336
#define ATT_SMB (ATT_SMF * 4)

__global__ void __launch_bounds__(256, 2) attn_mma_kernel() {
    extern __shared__ float sm[];
    const uint32_t smb = smem_u32(sm);
    const int sh = blockIdx.y;
    const int s = sh >> 3, h = sh & 7;
    const int qb = blockIdx.x;
    const int tid = threadIdx.x;
    const int lane = tid & 31, wid = tid >> 5;
    const int gid = lane >> 2, tg = lane & 3;
    const int wrow = wid * 16;

    // prologue: stage Q (128x32) + K/V tile 0 via cp.async
    const float* qg = g_q + ((size_t)(s * R_RES + qb * 128)) * HC + h * CH;
    {
#pragma unroll
        for (int it = 0; it < 4; it++) {
            int i = tid + it * 256;
            int r = i >> 3, c4 = i & 7;
            cp16(smb + (uint32_t)((ATT_QS + r * 36 + c4 * 4) * 4), qg + (size_t)r * HC + c4 * 4);
        }
        const float* kg = g_k + ((size_t)(s * R_RES)) * HC + h * CH;
        const float* vg = g_v + ((size_t)(s * R_RES)) * HC + h * CH;
#pragma unroll
        for (int it = 0; it < 2; it++) {
            int i = tid + it * 256;
            int r = i >> 3, c4 = i & 7;
            cp16(smb + (uint32_t)((ATT_KS + r * 36 + c4 * 4) * 4), kg + (size_t)r * HC + c4 * 4);
            cp16(smb + (uint32_t)((ATT_VS + r * 40 + c4 * 4) * 4), vg + (size_t)r * HC + c4 * 4);
        }
        asm volatile("cp.async.commit_group;" ::: "memory");
        asm volatile("cp.async.wait_group 0;" ::: "memory");
        __syncthreads();
    }

    uint32_t qa[4][4];
#pragma unroll
    for (int ks = 0; ks < 4; ks++) {
        int r0 = wrow + gid;
        qa[ks][0] = __float_as_uint(sm[ATT_QS + r0 * 36 + ks * 8 + tg]);
        qa[ks][1] = __float_as_uint(sm[ATT_QS + (r0 + 8) * 36 + ks * 8 + tg]);
        qa[ks][2] = __float_as_uint(sm[ATT_QS + r0 * 36 + ks * 8 + tg + 4]);
        qa[ks][3] = __float_as_uint(sm[ATT_QS + (r0 + 8) * 36 + ks * 8 + tg + 4]);
    }

    float m_i[2] = {-3.0e38f, -3.0e38f};
    float l_i[2] = {0.f, 0.f};
    float accO[4][4];
#pragma unroll
    for (int ct = 0; ct < 4; ct++)
#pragma unroll
        for (int j = 0; j < 4; j++) accO[ct][j] = 0.f;

    const float scale = 0.17677669529663687f * LOG2E;   // exp2 domain
    const float* bias_r0 = g_bias + ((size_t)h * R_RES + qb * 128 + wrow + gid) * R_RES;
    const float* bias_r1 = bias_r0 + 8 * R_RES;

#pragma unroll 1
    for (int kt = 0; kt < 4; kt++) {
        const int buf = kt & 1;
        // stage next K/V tile (other buffer) overlapped with this tile's compute
        if (kt < 3) {
            const float* kg = g_k + ((size_t)(s * R_RES + (kt + 1) * 64)) * HC + h * CH;
            const float* vg = g_v + ((size_t)(s * R_RES + (kt + 1) * 64)) * HC + h * CH;
            const int ko = ATT_KS + (buf ^ 1) * 2304;
            const int vo = ATT_VS + (buf ^ 1) * 2560;
#pragma unroll
            for (int it = 0; it < 2; it++) {
                int i = tid + it * 256;
                int r = i >> 3, c4 = i & 7;
                cp16(smb + (uint32_t)((ko + r * 36 + c4 * 4) * 4), kg + (size_t)r * HC + c4 * 4);
                cp16(smb + (uint32_t)((vo + r * 40 + c4 * 4) * 4), vg + (size_t)r * HC + c4 * 4);
            }
            asm volatile("cp.async.commit_group;" ::: "memory");
        }

        const float* Ks = sm + ATT_KS + buf * 2304;
        const float* Vs = sm + ATT_VS + buf * 2560;

        float acc[8][4];
#pragma unroll
        for (int nt = 0; nt < 8; nt++)
#pragma unroll
            for (int j = 0; j < 4; j++) acc[nt][j] = 0.f;

#pragma unroll
        for (int nt = 0; nt < 8; nt++) {
            const float* kr = &Ks[(nt * 8 + gid) * 36 + tg];
            uint32_t b[2];
#pragma unroll
            for (int ks = 0; ks < 4; ks++) {
                b[0] = __float_as_uint(kr[ks * 8]);
                b[1] = __float_as_uint(kr[ks * 8 + 4]);
                MMA4(acc[nt], qa[ks], b);
            }
        }

        float2 bb0[8], bb1[8];
#pragma unroll
        for (int nt = 0; nt < 8; nt++) {
            int col = kt * 64 + nt * 8 + 2 * tg;
            bb0[nt] = *(const float2*)&bias_r0[col];
            bb1[nt] = *(const float2*)&bias_r1[col];
        }
#pragma unroll
        for (int nt = 0; nt < 8; nt++) {
            acc[nt][0] = fmaf(acc[nt][0], scale, bb0[nt].x);
            acc[nt][1] = fmaf(acc[nt][1], scale, bb0[nt].y);
            acc[nt][2] = fmaf(acc[nt][2], scale, bb1[nt].x);
            acc[nt][3] = fmaf(acc[nt][3], scale, bb1[nt].y);
        }

        float mt[2] = {-3.0e38f, -3.0e38f};
#pragma unroll
        for (int nt = 0; nt < 8; nt++) {
            mt[0] = fmaxf(mt[0], fmaxf(acc[nt][0], acc[nt][1]));
            mt[1] = fmaxf(mt[1], fmaxf(acc[nt][2], acc[nt][3]));
        }
#pragma unroll
        for (int rh = 0; rh < 2; rh++) {
            mt[rh] = fmaxf(mt[rh], __shfl_xor_sync(0xffffffff, mt[rh], 1));
            mt[rh] = fmaxf(mt[rh], __shfl_xor_sync(0xffffffff, mt[rh], 2));
            float mnew = fmaxf(m_i[rh], mt[rh]);
            float corr = fexp2(m_i[rh] - mnew);
            m_i[rh] = mnew;
            l_i[rh] *= corr;
#pragma unroll
            for (int ct = 0; ct < 4; ct++) {
                accO[ct][rh * 2 + 0] *= corr;
                accO[ct][rh * 2 + 1] *= corr;
            }
        }
#pragma unroll
        for (int nt = 0; nt < 8; nt++) {
            acc[nt][0] = fexp2(acc[nt][0] - m_i[0]);
            acc[nt][1] = fexp2(acc[nt][1] - m_i[0]);
            acc[nt][2] = fexp2(acc[nt][2] - m_i[1]);
            acc[nt][3] = fexp2(acc[nt][3] - m_i[1]);
            l_i[0] += acc[nt][0] + acc[nt][1];
            l_i[1] += acc[nt][2] + acc[nt][3];
        }

        const int src = 4 * gid + (tg >> 1);
        const bool odd = tg & 1;
#pragma unroll
        for (int nt = 0; nt < 8; nt++) {
            float v0  = __shfl_sync(0xffffffff, acc[nt][0], src);
            float v1  = __shfl_sync(0xffffffff, acc[nt][1], src);
            float w0  = __shfl_sync(0xffffffff, acc[nt][2], src);
            float w1  = __shfl_sync(0xffffffff, acc[nt][3], src);
            float v0b = __shfl_sync(0xffffffff, acc[nt][0], src + 2);
            float v1b = __shfl_sync(0xffffffff, acc[nt][1], src + 2);
            float w0b = __shfl_sync(0xffffffff, acc[nt][2], src + 2);
            float w1b = __shfl_sync(0xffffffff, acc[nt][3], src + 2);
            uint32_t pa[4];
            pa[0] = ftf32u(odd ? v1 : v0);
            pa[1] = ftf32u(odd ? w1 : w0);
            pa[2] = ftf32u(odd ? v1b : v0b);
            pa[3] = ftf32u(odd ? w1b : w0b);
            const float* vr = &Vs[(nt * 8 + tg) * 40 + gid];
            uint32_t b[2];
#pragma unroll
            for (int ct = 0; ct < 4; ct++) {
                b[0] = __float_as_uint(vr[ct * 8]);
                b[1] = __float_as_uint(vr[ct * 8 + 160]);
                MMA4(accO[ct], pa, b);
            }
        }

        if (kt < 3) {
            asm volatile("cp.async.wait_group 0;" ::: "memory");
            __syncthreads();
        }
    }

    float inv[2];
#pragma unroll
    for (int rh = 0; rh < 2; rh++) {
        float l = l_i[rh];
        l += __shfl_xor_sync(0xffffffff, l, 1);
        l += __shfl_xor_sync(0xffffffff, l, 2);
        inv[rh] = 1.0f / l;
    }

    // stage gated output into smem (Qs region; 128 x 32, stride 36)
#pragma unroll
    for (int ct = 0; ct < 4; ct++) {
#pragma unroll
        for (int rh = 0; rh < 2; rh++) {
            int rl = wrow + gid + rh * 8;
            int grow = s * R_RES + qb * 128 + rl;
            int cl = ct * 8 + 2 * tg;
            float2 gt = *(const float2*)&g_gate[(size_t)grow * 256 + h * CH + cl];
            sm[ATT_QS + rl * 36 + cl]     = ftf32(accO[ct][rh * 2 + 0] * inv[rh] * gt.x);
            sm[ATT_QS + rl * 36 + cl + 1] = ftf32(accO[ct][rh * 2 + 1] * inv[rh] * gt.y);
        }
    }
    __syncthreads();

    // emit fragment-ordered, fully coalesced float4 stores
    const int f = tid * 4;
    const int kc = f >> 8, rem = f & 255;
    const int mt2 = rem >> 7, lp = (rem >> 2) & 31;
    const int gid2 = lp >> 2, tg2 = lp & 3;
    const int cb = kc * 8 + tg2;
#pragma unroll
    for (int it = 0; it < 4; it++) {
        int rbase = it * 32 + mt2 * 16 + gid2;
        float4 v;
        v.x = sm[ATT_QS + rbase * 36 + cb];
        v.y = sm[ATT_QS + (rbase + 8) * 36 + cb];
        v.z = sm[ATT_QS + rbase * 36 + cb + 4];
        v.w = sm[ATT_QS + (rbase + 8) * 36 + cb + 4];
        size_t rbg = (size_t)(s * 8 + qb * 4 + it);
        *(float4*)(g_of + rbg * 8192 + h * 1024 + f) = v;
    }
}

// ---------------- launch ----------------
extern "C" void kernel_launch(void* const* d_in, const int* in_sizes, int n_in,
                              void* d_out, int out_size) {
    (void)in_sizes; (void)n_in; (void)out_size;
    const float* m   = (const float*)d_in[0];
    const float* z   = (const float*)d_in[1];
    const float* lmw = (const float*)d_in[2];
    const float* lmb = (const float*)d_in[3];
    const float* lzw = (const float*)d_in[4];
    const float* lzb = (const float*)d_in[5];
    const float* Wz  = (const float*)d_in[6];
    const float* Wq  = (const float*)d_in[7];
    const float* Wk  = (const float*)d_in[8];
    const float* Wv  = (const float*)d_in[9];
    const float* Wg  = (const float*)d_in[10];
    const float* bg  = (const float*)d_in[11];
    const float* Wo  = (const float*)d_in[12];
    const float* bo  = (const float*)d_in[13];

    cudaFuncSetAttribute(tf32gemm_kernel, cudaFuncAttributeMaxDynamicSharedMemorySize, SM_BYTES);
    cudaFuncSetAttribute(attn_mma_kernel, cudaFuncAttributeMaxDynamicSharedMemorySize, ATT_SMB);

    prep_kernel<<<10560, 256>>>(m, lmw, lmb, z, lzw, lzb, Wz, Wq, Wk, Wv, Wg, Wo);

    tf32gemm_kernel<<<dim3(8, 512), 256, SM_BYTES>>>(bg, nullptr, nullptr, 1);

    attn_mma_kernel<<<dim3(2, S_SEQ * NH), 256, ATT_SMB>>>();

    tf32gemm_kernel<<<dim3(2, 512), 256, SM_BYTES>>>(nullptr, bo, (float*)d_out, 0);
}

// round 10
// speedup vs baseline: 1.7188x; 1.0182x over previous
#include <cuda_runtime.h>
#include <math.h>
#include <stdint.h>

#define S_SEQ 256
#define R_RES 256
#define CM 256
#define CZ 128
#define NH 8
#define CH 32
#define HC 256
#define LNEPS 1e-5f
#define LOG2E 1.4426950408889634f

// ---------------- scratch (device globals; no allocation allowed) ----------------
__device__ float g_mnf[(size_t)S_SEQ * R_RES * CM];      // 64 MB  LN(m), tf32, frag layout
__device__ float g_q[(size_t)S_SEQ * R_RES * HC];        // 64 MB  flat (s, r, h*32+c), tf32
__device__ float g_k[(size_t)S_SEQ * R_RES * HC];        // 64 MB  tf32
__device__ float g_v[(size_t)S_SEQ * R_RES * HC];        // 64 MB  tf32
__device__ float g_gate[(size_t)S_SEQ * R_RES * HC];     // 64 MB  sigmoid(mn@Wg+bg)
__device__ float g_of[(size_t)S_SEQ * R_RES * HC];       // 64 MB  gate .* attn_out, tf32, frag layout
__device__ float g_bias[(size_t)NH * R_RES * R_RES];     //  2 MB  [h][q][k], pre-scaled by log2e
__device__ float4 g_wf4[5 * 16384];                      //  2.5 MB B frags

__device__ __forceinline__ float ftf32(float x) {
    uint32_t u;
    asm("cvt.rna.tf32.f32 %0, %1;" : "=r"(u) : "f"(x));
    return __uint_as_float(u);
}
__device__ __forceinline__ float fexp2(float x) {
    float r;
    asm("ex2.approx.f32 %0, %1;" : "=f"(r) : "f"(x));
    return r;
}
__device__ __forceinline__ uint32_t smem_u32(const void* p) {
    uint32_t a;
    asm("{ .reg .u64 t; cvta.to.shared.u64 t, %1; cvt.u32.u64 %0, t; }" : "=r"(a) : "l"(p));
    return a;
}
__device__ __forceinline__ void cp16(uint32_t dst, const void* src) {
    asm volatile("cp.async.cg.shared.global [%0], [%1], 16;" :: "r"(dst), "l"(src));
}

#define MMA4(d, a, b)                                                              \
    asm volatile("mma.sync.aligned.m16n8k8.row.col.f32.tf32.tf32.f32 "             \
                 "{%0,%1,%2,%3},{%4,%5,%6,%7},{%8,%9},{%0,%1,%2,%3};"              \
                 : "+f"(d[0]), "+f"(d[1]), "+f"(d[2]), "+f"(d[3])                  \
                 : "r"(a[0]), "r"(a[1]), "r"(a[2]), "r"(a[3]), "r"(b[0]), "r"(b[1]))

// ================= prep mega-kernel: ln_m (0..2047) | ln_z+bias (2048..10239) | repack =====
__global__ void __launch_bounds__(256) prep_kernel(
    const float* __restrict__ x, const float* __restrict__ lmw, const float* __restrict__ lmb,
    const float* __restrict__ z, const float* __restrict__ lzw, const float* __restrict__ lzb,
    const float* __restrict__ Wz,
    const float* __restrict__ w0, const float* __restrict__ w1, const float* __restrict__ w2,
    const float* __restrict__ w3, const float* __restrict__ w4) {

    __shared__ float sh[32 * 260];
    const int tid = threadIdx.x;
    const int wid = tid >> 5, lane = tid & 31;
    const int bx = blockIdx.x;

    if (bx < 2048) {
        // ---- LayerNorm m -> fragment-ordered tf32 g_mnf ----
        const float4 w0v = *(const float4*)(lmw + lane * 8);
        const float4 w1v = *(const float4*)(lmw + lane * 8 + 4);
        const float4 b0v = *(const float4*)(lmb + lane * 8);
        const float4 b1v = *(const float4*)(lmb + lane * 8 + 4);
#pragma unroll 1
        for (int q = 0; q < 4; q++) {
            int lr = wid * 4 + q;
            size_t row = (size_t)bx * 32 + lr;
            const float* xp = x + row * CM + lane * 8;
            float4 v0 = *(const float4*)xp;
            float4 v1 = *(const float4*)(xp + 4);
            float s  = v0.x + v0.y + v0.z + v0.w + v1.x + v1.y + v1.z + v1.w;
            float sq = v0.x * v0.x + v0.y * v0.y + v0.z * v0.z + v0.w * v0.w
                     + v1.x * v1.x + v1.y * v1.y + v1.z * v1.z + v1.w * v1.w;
#pragma unroll
            for (int st = 16; st > 0; st >>= 1) {
                s  += __shfl_xor_sync(0xffffffff, s, st);
                sq += __shfl_xor_sync(0xffffffff, sq, st);
            }
            float mean = s * (1.0f / CM);
            float inv  = rsqrtf(sq * (1.0f / CM) - mean * mean + LNEPS);
            float* sp = &sh[lr * 260 + lane * 8];
            sp[0] = ftf32((v0.x - mean) * inv * w0v.x + b0v.x);
            sp[1] = ftf32((v0.y - mean) * inv * w0v.y + b0v.y);
            sp[2] = ftf32((v0.z - mean) * inv * w0v.z + b0v.z);
            sp[3] = ftf32((v0.w - mean) * inv * w0v.w + b0v.w);
            sp[4] = ftf32((v1.x - mean) * inv * w1v.x + b1v.x);
            sp[5] = ftf32((v1.y - mean) * inv * w1v.y + b1v.y);
            sp[6] = ftf32((v1.z - mean) * inv * w1v.z + b1v.z);
            sp[7] = ftf32((v1.w - mean) * inv * w1v.w + b1v.w);
        }
        __syncthreads();

        float* dst = g_mnf + (size_t)bx * 8192;
#pragma unroll
        for (int it = 0; it < 8; it++) {
            int i = tid + it * 256;
            int f = i * 4;
            int kc = f >> 8, rem = f & 255;
            int mt = rem >> 7, lp = (rem >> 2) & 31;
            int gid2 = lp >> 2, tg2 = lp & 3;
            int cb = kc * 8 + tg2;
            float4 v;
            v.x = sh[(mt * 16 + 0 + gid2) * 260 + cb];
            v.y = sh[(mt * 16 + 8 + gid2) * 260 + cb];
            v.z = sh[(mt * 16 + 0 + gid2) * 260 + cb + 4];
            v.w = sh[(mt * 16 + 8 + gid2) * 260 + cb + 4];
            *(float4*)(dst + f) = v;
        }
    } else if (bx < 10240) {
        // ---- LN(z) + pair-bias (pre-scaled by log2e): one warp per (q,k) ----
        for (int i = tid; i < 1024; i += 256) {
            int zz = i >> 3, h = i & 7;
            sh[h * 128 + zz] = Wz[i];
        }
        __syncthreads();

        const int qk = (bx - 2048) * 8 + wid;
        const int q = qk >> 8, k = qk & 255;
        float4 v = *(const float4*)(z + (size_t)qk * CZ + 4 * lane);
        float s  = v.x + v.y + v.z + v.w;
        float sq = v.x * v.x + v.y * v.y + v.z * v.z + v.w * v.w;
#pragma unroll
        for (int st = 16; st > 0; st >>= 1) {
            s  += __shfl_xor_sync(0xffffffff, s, st);
            sq += __shfl_xor_sync(0xffffffff, sq, st);
        }
        float mean = s * (1.0f / CZ);
        float inv  = rsqrtf(sq * (1.0f / CZ) - mean * mean + LNEPS);
        float4 w4 = *(const float4*)(lzw + 4 * lane);
        float4 b4 = *(const float4*)(lzb + 4 * lane);
        float4 zn;
        zn.x = (v.x - mean) * inv * w4.x + b4.x;
        zn.y = (v.y - mean) * inv * w4.y + b4.y;
        zn.z = (v.z - mean) * inv * w4.z + b4.z;
        zn.w = (v.w - mean) * inv * w4.w + b4.w;

        float p[8];
#pragma unroll
        for (int h = 0; h < 8; h++) {
            float4 wz = *(const float4*)&sh[h * 128 + 4 * lane];
            p[h] = zn.x * wz.x + zn.y * wz.y + zn.z * wz.z + zn.w * wz.w;
        }
#pragma unroll
        for (int st = 16; st > 0; st >>= 1) {
#pragma unroll
            for (int h = 0; h < 8; h++) p[h] += __shfl_xor_sync(0xffffffff, p[h], st);
        }
        float outv = p[0];
#pragma unroll
        for (int h = 1; h < 8; h++) if (lane == h) outv = p[h];
        if (lane < 8)
            g_bias[((size_t)lane * R_RES + q) * R_RES + k] = outv * LOG2E;
    } else {
        // ---- B-fragment repack ----
        int t = (bx - 10240) * 256 + tid;       // < 81920
        int ln2 = t & 31;
        int ntp = (t >> 5) & 1;
        int ks = (t >> 6) & 3;
        int nb = (t >> 8) & 7;
        int kt = (t >> 11) & 7;
        int zz = t >> 14;
        const float* W = (zz == 0) ? w0 : (zz == 1) ? w1 : (zz == 2) ? w2 : (zz == 3) ? w3 : w4;
        int krow = kt * 32 + ks * 8 + (ln2 & 3);
        int gidr = ln2 >> 2;
        int ncolA = nb * 32 + (2 * ntp) * 8 + gidr;
        int ncolB = ncolA + 8;
        float4 v;
        v.x = ftf32(W[krow * 256 + ncolA]);
        v.y = ftf32(W[(krow + 4) * 256 + ncolA]);
        v.z = ftf32(W[krow * 256 + ncolB]);
        v.w = ftf32(W[(krow + 4) * 256 + ncolB]);
        g_wf4[t] = v;
    }
}

// ---------------- cp.async-pipelined tf32 GEMM: C(65536x256) = A @ W ----------------
#define ASTAGE_F 4096
#define STAGE_F  8192
#define SM_BYTES (3 * STAGE_F * 4)   // 98304

__device__ __forceinline__ void stage_tile(uint32_t smb, int buf, int kt, int by, int nbp2,
                                           int tid, const float* Af, const float4* Bw) {
    uint32_t db = smb + (uint32_t)buf * (STAGE_F * 4);
#pragma unroll
    for (int it = 0; it < 4; it++) {
        int ca = tid + it * 256;
        int rb = ca >> 8, kc = (ca >> 6) & 3, c = ca & 63;
        const float* s = Af + ((size_t)(by * 128 + rb * 32 + kt * 4 + kc)) * 256 + c * 4;
        cp16(db + (uint32_t)(((rb * 4 + kc) * 256 + c * 4) * 4), s);
    }
#pragma unroll
    for (int it = 0; it < 4; it++) {
        int cb = tid + it * 256;
        int nl = cb >> 8, inner = cb & 255;
        const float4* s = Bw + ((size_t)(kt * 8 + nbp2 * 4 + nl)) * 256 + inner;
        cp16(db + (uint32_t)((ASTAGE_F + nl * 1024 + inner * 4) * 4), s);
    }
}

__global__ void __launch_bounds__(256, 2) tf32gemm_kernel(
    const float* __restrict__ bias_g, const float* __restrict__ bias_o,
    float* __restrict__ out_ext, int fused) {

    extern __shared__ float sm[];
    const uint32_t smb = smem_u32(sm);
    const int tid = threadIdx.x;
    const int lane = tid & 31, wid = tid >> 5;
    const int gid = lane >> 2, tg = lane & 3;
    const int rbw = wid & 3;
    const int nblw = wid >> 2;
    const int nbp2 = fused ? (blockIdx.x >> 2) : blockIdx.x;
    const int zz  = fused ? (blockIdx.x & 3) : 4;
    const int by  = blockIdx.y;

    const float* Af = fused ? g_mnf : g_of;
    const float4* Bw = g_wf4 + (size_t)zz * 16384;

    float acc[2][8][4];
#pragma unroll
    for (int mt = 0; mt < 2; mt++)
#pragma unroll
        for (int nt = 0; nt < 8; nt++)
#pragma unroll
            for (int j = 0; j < 4; j++) acc[mt][nt][j] = 0.f;

    stage_tile(smb, 0, 0, by, nbp2, tid, Af, Bw);
    asm volatile("cp.async.commit_group;" ::: "memory");
    stage_tile(smb, 1, 1, by, nbp2, tid, Af, Bw);
    asm volatile("cp.async.commit_group;" ::: "memory");

    int cur = 0, nxt = 2;
#pragma unroll 1
    for (int kt = 0; kt < 8; kt++) {
        asm volatile("cp.async.wait_group 1;" ::: "memory");
        __syncthreads();
        if (kt < 6) stage_tile(smb, nxt, kt + 2, by, nbp2, tid, Af, Bw);
        asm volatile("cp.async.commit_group;" ::: "memory");

        const float* As = sm + cur * STAGE_F;
        const float* Bs = As + ASTAGE_F;
#pragma unroll
        for (int kc = 0; kc < 4; kc++) {
            float4 va0 = *(const float4*)&As[(rbw * 4 + kc) * 256 + lane * 4];
            float4 va1 = *(const float4*)&As[(rbw * 4 + kc) * 256 + 128 + lane * 4];
            uint32_t a0[4] = {__float_as_uint(va0.x), __float_as_uint(va0.y),
                              __float_as_uint(va0.z), __float_as_uint(va0.w)};
            uint32_t a1[4] = {__float_as_uint(va1.x), __float_as_uint(va1.y),
                              __float_as_uint(va1.z), __float_as_uint(va1.w)};
#pragma unroll
            for (int nbl2 = 0; nbl2 < 2; nbl2++) {
                const int nbloc = nblw * 2 + nbl2;
#pragma unroll
                for (int ntp = 0; ntp < 2; ntp++) {
                    float4 vb = *(const float4*)&Bs[nbloc * 1024 + ((kc * 2 + ntp) * 32 + lane) * 4];
                    uint32_t b0[2] = {__float_as_uint(vb.x), __float_as_uint(vb.y)};
                    uint32_t b1[2] = {__float_as_uint(vb.z), __float_as_uint(vb.w)};
                    const int nt = nbl2 * 4 + 2 * ntp;
                    MMA4(acc[0][nt], a0, b0);
                    MMA4(acc[1][nt], a1, b0);
                    MMA4(acc[0][nt + 1], a0, b1);
                    MMA4(acc[1][nt + 1], a1, b1);
                }
            }
        }
        cur = (cur == 2) ? 0 : cur + 1;
        nxt = (nxt == 2) ? 0 : nxt + 1;
    }

    // ---- epilogue ----
    float* out = (!fused) ? out_ext
               : (zz == 0) ? g_q : (zz == 1) ? g_k : (zz == 2) ? g_v : g_gate;
#pragma unroll
    for (int mt = 0; mt < 2; mt++) {
#pragma unroll
        for (int nt = 0; nt < 8; nt++) {
#pragma unroll
            for (int half = 0; half < 2; half++) {
                int gr = by * 128 + rbw * 32 + mt * 16 + gid + half * 8;
                int gc = nbp2 * 128 + (nblw * 2 + (nt >> 2)) * 32 + (nt & 3) * 8 + tg * 2;
                float2 val;
                val.x = acc[mt][nt][half * 2 + 0];
                val.y = acc[mt][nt][half * 2 + 1];
                if (fused && zz == 3) {
                    val.x = 1.f / (1.f + __expf(-(val.x + bias_g[gc + 0])));
                    val.y = 1.f / (1.f + __expf(-(val.y + bias_g[gc + 1])));
                } else if (!fused) {
                    val.x += bias_o[gc + 0];
                    val.y += bias_o[gc + 1];
                } else {
                    val.x = ftf32(val.x);     // pre-round q/k/v for attention
                    val.y = ftf32(val.y);
                }
                *(float2*)(out + (size_t)gr * 256 + gc) = val;
            }
        }
    }
}

// ---------------- tensor-core flash attention: cp.async pipeline, smem P-staging ----------
// dynamic smem: Qs/Ps[128*36]=4608 | Ks[2][64*36]=4608 | Vs[2][64*40]=5120  (14336 floats)
#define ATT_QS 0
#define ATT_KS 4608
#define ATT_VS 9216
#define ATT_SMF 14336
#define ATT_SMB (ATT_SMF * 4)

__global__ void __launch_bounds__(256, 2) attn_mma_kernel() {
    extern __shared__ float sm[];
    const uint32_t smb = smem_u32(sm);
    const int sh = blockIdx.y;
    const int s = sh >> 3, h = sh & 7;
    const int qb = blockIdx.x;
    const int tid = threadIdx.x;
    const int lane = tid & 31, wid = tid >> 5;
    const int gid = lane >> 2, tg = lane & 3;
    const int wrow = wid * 16;

    // prologue: stage Q (128x32) + K/V tile 0 via cp.async
    const float* qg = g_q + ((size_t)(s * R_RES + qb * 128)) * HC + h * CH;
    {
#pragma unroll
        for (int it = 0; it < 4; it++) {
            int i = tid + it * 256;
            int r = i >> 3, c4 = i & 7;
            cp16(smb + (uint32_t)((ATT_QS + r * 36 + c4 * 4) * 4), qg + (size_t)r * HC + c4 * 4);
        }
        const float* kg = g_k + ((size_t)(s * R_RES)) * HC + h * CH;
        const float* vg = g_v + ((size_t)(s * R_RES)) * HC + h * CH;
#pragma unroll
        for (int it = 0; it < 2; it++) {
            int i = tid + it * 256;
            int r = i >> 3, c4 = i & 7;
            cp16(smb + (uint32_t)((ATT_KS + r * 36 + c4 * 4) * 4), kg + (size_t)r * HC + c4 * 4);
            cp16(smb + (uint32_t)((ATT_VS + r * 40 + c4 * 4) * 4), vg + (size_t)r * HC + c4 * 4);
        }
        asm volatile("cp.async.commit_group;" ::: "memory");
        asm volatile("cp.async.wait_group 0;" ::: "memory");
        __syncthreads();
    }

    uint32_t qa[4][4];
#pragma unroll
    for (int ks = 0; ks < 4; ks++) {
        int r0 = wrow + gid;
        qa[ks][0] = __float_as_uint(sm[ATT_QS + r0 * 36 + ks * 8 + tg]);
        qa[ks][1] = __float_as_uint(sm[ATT_QS + (r0 + 8) * 36 + ks * 8 + tg]);
        qa[ks][2] = __float_as_uint(sm[ATT_QS + r0 * 36 + ks * 8 + tg + 4]);
        qa[ks][3] = __float_as_uint(sm[ATT_QS + (r0 + 8) * 36 + ks * 8 + tg + 4]);
    }
    __syncthreads();   // Q frags extracted; Qs region becomes the P staging area

    float m_i[2] = {-3.0e38f, -3.0e38f};
    float l_i[2] = {0.f, 0.f};
    float accO[4][4];
#pragma unroll
    for (int ct = 0; ct < 4; ct++)
#pragma unroll
        for (int j = 0; j < 4; j++) accO[ct][j] = 0.f;

    const float scale = 0.17677669529663687f * LOG2E;   // exp2 domain
    const float* bias_r0 = g_bias + ((size_t)h * R_RES + qb * 128 + wrow + gid) * R_RES;
    const float* bias_r1 = bias_r0 + 8 * R_RES;

#pragma unroll 1
    for (int kt = 0; kt < 4; kt++) {
        const int buf = kt & 1;
        // stage next K/V tile (other buffer) overlapped with this tile's compute
        if (kt < 3) {
            const float* kg = g_k + ((size_t)(s * R_RES + (kt + 1) * 64)) * HC + h * CH;
            const float* vg = g_v + ((size_t)(s * R_RES + (kt + 1) * 64)) * HC + h * CH;
            const int ko = ATT_KS + (buf ^ 1) * 2304;
            const int vo = ATT_VS + (buf ^ 1) * 2560;
#pragma unroll
            for (int it = 0; it < 2; it++) {
                int i = tid + it * 256;
                int r = i >> 3, c4 = i & 7;
                cp16(smb + (uint32_t)((ko + r * 36 + c4 * 4) * 4), kg + (size_t)r * HC + c4 * 4);
                cp16(smb + (uint32_t)((vo + r * 40 + c4 * 4) * 4), vg + (size_t)r * HC + c4 * 4);
            }
            asm volatile("cp.async.commit_group;" ::: "memory");
        }

        const float* Ks = sm + ATT_KS + buf * 2304;
        const float* Vs = sm + ATT_VS + buf * 2560;

        // hoisted bias loads (independent of MMA results; hides L2 latency)
        float2 bb0[8], bb1[8];
#pragma unroll
        for (int nt = 0; nt < 8; nt++) {
            int col = kt * 64 + nt * 8 + 2 * tg;
            bb0[nt] = *(const float2*)&bias_r0[col];
            bb1[nt] = *(const float2*)&bias_r1[col];
        }

        float acc[8][4];
#pragma unroll
        for (int nt = 0; nt < 8; nt++)
#pragma unroll
            for (int j = 0; j < 4; j++) acc[nt][j] = 0.f;

#pragma unroll
        for (int nt = 0; nt < 8; nt++) {
            const float* kr = &Ks[(nt * 8 + gid) * 36 + tg];
            uint32_t b[2];
#pragma unroll
            for (int ks = 0; ks < 4; ks++) {
                b[0] = __float_as_uint(kr[ks * 8]);
                b[1] = __float_as_uint(kr[ks * 8 + 4]);
                MMA4(acc[nt], qa[ks], b);
            }
        }

#pragma unroll
        for (int nt = 0; nt < 8; nt++) {
            acc[nt][0] = fmaf(acc[nt][0], scale, bb0[nt].x);
            acc[nt][1] = fmaf(acc[nt][1], scale, bb0[nt].y);
            acc[nt][2] = fmaf(acc[nt][2], scale, bb1[nt].x);
            acc[nt][3] = fmaf(acc[nt][3], scale, bb1[nt].y);
        }

        float mt[2] = {-3.0e38f, -3.0e38f};
#pragma unroll
        for (int nt = 0; nt < 8; nt++) {
            mt[0] = fmaxf(mt[0], fmaxf(acc[nt][0], acc[nt][1]));
            mt[1] = fmaxf(mt[1], fmaxf(acc[nt][2], acc[nt][3]));
        }
#pragma unroll
        for (int rh = 0; rh < 2; rh++) {
            mt[rh] = fmaxf(mt[rh], __shfl_xor_sync(0xffffffff, mt[rh], 1));
            mt[rh] = fmaxf(mt[rh], __shfl_xor_sync(0xffffffff, mt[rh], 2));
            float mnew = fmaxf(m_i[rh], mt[rh]);
            float corr = fexp2(m_i[rh] - mnew);
            m_i[rh] = mnew;
            l_i[rh] *= corr;
#pragma unroll
            for (int ct = 0; ct < 4; ct++) {
                accO[ct][rh * 2 + 0] *= corr;
                accO[ct][rh * 2 + 1] *= corr;
            }
        }
#pragma unroll
        for (int nt = 0; nt < 8; nt++) {
            acc[nt][0] = fexp2(acc[nt][0] - m_i[0]);
            acc[nt][1] = fexp2(acc[nt][1] - m_i[0]);
            acc[nt][2] = fexp2(acc[nt][2] - m_i[1]);
            acc[nt][3] = fexp2(acc[nt][3] - m_i[1]);
            l_i[0] += acc[nt][0] + acc[nt][1];
            l_i[1] += acc[nt][2] + acc[nt][3];
        }

        // P relayout via per-warp smem staging (rows wrow..wrow+15 of Ps, 32 cols per half)
#pragma unroll
        for (int half = 0; half < 2; half++) {
#pragma unroll
            for (int n4 = 0; n4 < 4; n4++) {
                const int nt = half * 4 + n4;
                float2 p01, p23;
                p01.x = ftf32(acc[nt][0]); p01.y = ftf32(acc[nt][1]);
                p23.x = ftf32(acc[nt][2]); p23.y = ftf32(acc[nt][3]);
                *(float2*)&sm[ATT_QS + (wrow + gid) * 36 + n4 * 8 + 2 * tg] = p01;
                *(float2*)&sm[ATT_QS + (wrow + gid + 8) * 36 + n4 * 8 + 2 * tg] = p23;
            }
            __syncwarp();
#pragma unroll
            for (int k4 = 0; k4 < 4; k4++) {
                uint32_t pa[4];
                pa[0] = __float_as_uint(sm[ATT_QS + (wrow + gid) * 36 + k4 * 8 + tg]);
                pa[1] = __float_as_uint(sm[ATT_QS + (wrow + gid + 8) * 36 + k4 * 8 + tg]);
                pa[2] = __float_as_uint(sm[ATT_QS + (wrow + gid) * 36 + k4 * 8 + tg + 4]);
                pa[3] = __float_as_uint(sm[ATT_QS + (wrow + gid + 8) * 36 + k4 * 8 + tg + 4]);
                const int kchunk = half * 4 + k4;
                const float* vr = &Vs[(kchunk * 8 + tg) * 40 + gid];
                uint32_t b[2];
#pragma unroll
                for (int ct = 0; ct < 4; ct++) {
                    b[0] = __float_as_uint(vr[ct * 8]);
                    b[1] = __float_as_uint(vr[ct * 8 + 160]);
                    MMA4(accO[ct], pa, b);
                }
            }
            __syncwarp();
        }

        if (kt < 3) {
            asm volatile("cp.async.wait_group 0;" ::: "memory");
            __syncthreads();
        }
    }

    float inv[2];
#pragma unroll
    for (int rh = 0; rh < 2; rh++) {
        float l = l_i[rh];
        l += __shfl_xor_sync(0xffffffff, l, 1);
        l += __shfl_xor_sync(0xffffffff, l, 2);
        inv[rh] = 1.0f / l;
    }

    __syncthreads();   // all warps done with per-warp P staging before block-wide reuse

    // stage gated output into smem (Qs region; 128 x 32, stride 36)
#pragma unroll
    for (int ct = 0; ct < 4; ct++) {
#pragma unroll
        for (int rh = 0; rh < 2; rh++) {
            int rl = wrow + gid + rh * 8;
            int grow = s * R_RES + qb * 128 + rl;
            int cl = ct * 8 + 2 * tg;
            float2 gt = *(const float2*)&g_gate[(size_t)grow * 256 + h * CH + cl];
            sm[ATT_QS + rl * 36 + cl]     = ftf32(accO[ct][rh * 2 + 0] * inv[rh] * gt.x);
            sm[ATT_QS + rl * 36 + cl + 1] = ftf32(accO[ct][rh * 2 + 1] * inv[rh] * gt.y);
        }
    }
    __syncthreads();

    // emit fragment-ordered, fully coalesced float4 stores
    const int f = tid * 4;
    const int kc = f >> 8, rem = f & 255;
    const int mt2 = rem >> 7, lp = (rem >> 2) & 31;
    const int gid2 = lp >> 2, tg2 = lp & 3;
    const int cb = kc * 8 + tg2;
#pragma unroll
    for (int it = 0; it < 4; it++) {
        int rbase = it * 32 + mt2 * 16 + gid2;
        float4 v;
        v.x = sm[ATT_QS + rbase * 36 + cb];
        v.y = sm[ATT_QS + (rbase + 8) * 36 + cb];
        v.z = sm[ATT_QS + rbase * 36 + cb + 4];
        v.w = sm[ATT_QS + (rbase + 8) * 36 + cb + 4];
        size_t rbg = (size_t)(s * 8 + qb * 4 + it);
        *(float4*)(g_of + rbg * 8192 + h * 1024 + f) = v;
    }
}

// ---------------- launch ----------------
extern "C" void kernel_launch(void* const* d_in, const int* in_sizes, int n_in,
                              void* d_out, int out_size) {
    (void)in_sizes; (void)n_in; (void)out_size;
    const float* m   = (const float*)d_in[0];
    const float* z   = (const float*)d_in[1];
    const float* lmw = (const float*)d_in[2];
    const float* lmb = (const float*)d_in[3];
    const float* lzw = (const float*)d_in[4];
    const float* lzb = (const float*)d_in[5];
    const float* Wz  = (const float*)d_in[6];
    const float* Wq  = (const float*)d_in[7];
    const float* Wk  = (const float*)d_in[8];
    const float* Wv  = (const float*)d_in[9];
    const float* Wg  = (const float*)d_in[10];
    const float* bg  = (const float*)d_in[11];
    const float* Wo  = (const float*)d_in[12];
    const float* bo  = (const float*)d_in[13];

    cudaFuncSetAttribute(tf32gemm_kernel, cudaFuncAttributeMaxDynamicSharedMemorySize, SM_BYTES);
    cudaFuncSetAttribute(attn_mma_kernel, cudaFuncAttributeMaxDynamicSharedMemorySize, ATT_SMB);

    prep_kernel<<<10560, 256>>>(m, lmw, lmb, z, lzw, lzb, Wz, Wq, Wk, Wv, Wg, Wo);

    tf32gemm_kernel<<<dim3(8, 512), 256, SM_BYTES>>>(bg, nullptr, nullptr, 1);

    attn_mma_kernel<<<dim3(2, S_SEQ * NH), 256, ATT_SMB>>>();

    tf32gemm_kernel<<<dim3(2, 512), 256, SM_BYTES>>>(nullptr, bo, (float*)d_out, 0);
}